// round 13
// baseline (speedup 1.0000x reference)
#include <cuda_runtime.h>
#include <cuda_bf16.h>
#include <cuda_fp16.h>
#include <math.h>
#include <stdint.h>

#define Nn    20000
#define Ee    320000
#define DIMc  256
#define Hh    8
#define EDIMc 32
#define DFFc  1024
#define ETOT  (Ee + Nn)

// ---------------- scratch (device globals) -----------------------------------
static __device__ float    g_xlr[(size_t)Nn * 512];
static __device__ __half   g_xlrh[(size_t)Nn * 512];
static __device__ float    g_loop[(size_t)Nn * EDIMc];
static __device__ int      g_icnt[Nn];
static __device__ float    g_sc [(size_t)ETOT * Hh];
static __device__ float    g_agg[(size_t)Nn * DIMc];
static __device__ float    g_h1 [(size_t)Nn * DIMc];
static __device__ float    g_h2 [(size_t)Nn * DIMc];
static __device__ float    g_ff2[(size_t)Nn * DIMc];
static __device__ float    g_sum[DIMc];
static __device__ float    g_sumsq[DIMc];
static __device__ int      g_rowptr[Nn + 1];
static __device__ int      g_tmp[Nn];
static __device__ int2     g_adj[Ee];

static __device__ __nv_bfloat16 g_Apk[(size_t)Nn * 768];
static __device__ __nv_bfloat16 g_Fpk[(size_t)Nn * 3072];
static __device__ __nv_bfloat16 g_EApk[(size_t)ETOT * 64];   // [Ah|Al], Kp=64
#define OWLR1 0
#define OWE1  393216
#define OWLR2 409600
#define OWE2  802816
#define OW1   819200
#define OW2   1605632
#define WPK_TOTAL 2392064
static __device__ __nv_bfloat16 g_Wpk[WPK_TOTAL];

// ---------------- PTX helpers --------------------------------------------------
__device__ __forceinline__ uint32_t smem_u32(const void* p) {
    uint32_t a;
    asm("{ .reg .u64 t; cvta.to.shared.u64 t, %1; cvt.u32.u64 %0, t; }"
        : "=r"(a) : "l"(p));
    return a;
}
#define LDSM_X4(r0, r1, r2, r3, addr) \
    asm volatile("ldmatrix.sync.aligned.m8n8.x4.shared.b16 {%0,%1,%2,%3}, [%4];" \
                 : "=r"(r0), "=r"(r1), "=r"(r2), "=r"(r3) : "r"(addr))
#define LDSM_X2(r0, r1, addr) \
    asm volatile("ldmatrix.sync.aligned.m8n8.x2.shared.b16 {%0,%1}, [%2];" \
                 : "=r"(r0), "=r"(r1) : "r"(addr))
#define MMA16816(c, a0, a1, a2, a3, b0, b1) \
    asm volatile("mma.sync.aligned.m16n8k16.row.col.f32.bf16.bf16.f32 " \
                 "{%0,%1,%2,%3}, {%4,%5,%6,%7}, {%8,%9}, {%0,%1,%2,%3};" \
                 : "+f"((c)[0]), "+f"((c)[1]), "+f"((c)[2]), "+f"((c)[3]) \
                 : "r"(a0), "r"(a1), "r"(a2), "r"(a3), "r"(b0), "r"(b1))
__device__ __forceinline__ void cp_cg(uint32_t dst, const void* src, int sz) {
    asm volatile("cp.async.cg.shared.global [%0], [%1], 16, %2;"
                 :: "r"(dst), "l"(src), "r"(sz));
}
#define CP_COMMIT() asm volatile("cp.async.commit_group;" ::: "memory")
#define SMEM_SWZ(b) ((b) ^ (((b) >> 3) & 0x70))

// ---------------- pack kernels --------------------------------------------------
__global__ void k_pack_node(const float* __restrict__ X, __nv_bfloat16* __restrict__ A,
                            int rows, int K) {
    int i = blockIdx.x * blockDim.x + threadIdx.x;
    if (i >= rows * K) return;
    int r = i / K, k = i - r * K;
    float v = X[i];
    __nv_bfloat16 h = __float2bfloat16(v);
    __nv_bfloat16 l = __float2bfloat16(v - __bfloat162float(h));
    size_t b = (size_t)r * (3 * K);
    A[b + k] = h;
    A[b + K + k] = l;
    A[b + 2 * K + k] = h;
}
__global__ void k_pack_ea(const float* __restrict__ ew) {
    int i = blockIdx.x * blockDim.x + threadIdx.x;
    if (i >= ETOT * EDIMc) return;
    int r = i >> 5, k = i & 31;
    float v = (r < Ee) ? ew[i] : g_loop[(size_t)(r - Ee) * EDIMc + k];
    __nv_bfloat16 h = __float2bfloat16(v);
    __nv_bfloat16 l = __float2bfloat16(v - __bfloat162float(h));
    size_t b = (size_t)r * 64;
    g_EApk[b + k]      = h;
    g_EApk[b + 32 + k] = l;
}
__device__ __forceinline__ void pack_w_one(const float* __restrict__ W,
                                           __nv_bfloat16* __restrict__ WT,
                                           int i, int K, int N, int Kp) {
    int k = i / N, n = i - k * N;
    float v = W[i];
    __nv_bfloat16 h = __float2bfloat16(v);
    __nv_bfloat16 l = __float2bfloat16(v - __bfloat162float(h));
    size_t b = (size_t)n * Kp;
    WT[b + k]         = h;
    WT[b + K + k]     = h;
    WT[b + 2 * K + k] = l;
    if (k < Kp - 3 * K) WT[b + 3 * K + k] = __float2bfloat16(0.f);
}
__device__ __forceinline__ void pack_w_x2(const float* __restrict__ W,
                                          __nv_bfloat16* __restrict__ WT, int i) {
    int k = i >> 8, n = i & 255;
    __nv_bfloat16 h = __float2bfloat16(W[i]);
    WT[n * 64 + k]      = h;
    WT[n * 64 + 32 + k] = h;
}
__global__ void k_packT_all(const float* w0, const float* w1, const float* w2,
                            const float* w3, const float* w4, const float* w5,
                            const float* w6, const float* w7,
                            __nv_bfloat16* __restrict__ WT) {
    int i = blockIdx.x * blockDim.x + threadIdx.x;
    if (i < 65536)        pack_w_one(w0, WT + OWLR1,          i,           DIMc, DIMc, 768);
    else if (i < 131072)  pack_w_one(w1, WT + OWLR1 + 196608, i - 65536,   DIMc, DIMc, 768);
    else if (i < 139264)  pack_w_x2 (w2, WT + OWE1,           i - 131072);
    else if (i < 204800)  pack_w_one(w3, WT + OWLR2,          i - 139264,  DIMc, DIMc, 768);
    else if (i < 270336)  pack_w_one(w4, WT + OWLR2 + 196608, i - 204800,  DIMc, DIMc, 768);
    else if (i < 278528)  pack_w_x2 (w5, WT + OWE2,           i - 270336);
    else if (i < 540672)  pack_w_one(w6, WT + OW1,            i - 278528,  DIMc, DFFc, 768);
    else if (i < 802816)  pack_w_one(w7, WT + OW2,            i - 540672,  DFFc, DIMc, 3072);
}

// ---------------- 3-stage pipelined bf16 GEMM (K-packed x3) --------------------
#define GEMM_SMEM_PK 98304

template<int EPI>
__global__ void __launch_bounds__(256, 2) gemm_pk(
    const __nv_bfloat16* __restrict__ A, const __nv_bfloat16* __restrict__ BT,
    const float* __restrict__ bias, float* __restrict__ C,
    int M, int Kp, int Nc) {
    extern __shared__ __nv_bfloat16 sm[];
    __shared__ float s_st[512];
    uint32_t sb = smem_u32(sm);
    int tid  = threadIdx.x;
    int lane = tid & 31;
    int w    = tid >> 5;
    int wr   = w & 1;
    int wc   = w >> 1;
    int row0 = blockIdx.y * 128;
    int col0 = blockIdx.x * 128;

    if (EPI == 1 && blockIdx.x == 0 && blockIdx.y == 0 && tid < 256) {
        g_sum[tid] = 0.f; g_sumsq[tid] = 0.f;
    }
    if (EPI == 3) { s_st[tid] = 0.f; s_st[tid + 256] = 0.f; }

    float acc[4][4][4];
#pragma unroll
    for (int i = 0; i < 4; i++)
#pragma unroll
        for (int j = 0; j < 4; j++)
#pragma unroll
            for (int q = 0; q < 4; q++) acc[i][j][q] = 0.f;

    const int nch = Kp >> 6;

    auto issue = [&](int c) {
        if (c < nch) {
            int stage = c % 3;
            uint32_t sA = sb + (uint32_t)stage * 32768u;
            uint32_t sB = sA + 16384u;
            int k0 = c << 6;
#pragma unroll
            for (int p = 0; p < 4; p++) {
                int idx = tid + (p << 8);
                int row = idx >> 3, u = idx & 7;
                uint32_t soff = SMEM_SWZ((uint32_t)(row * 128 + u * 16));
                int gr = row0 + row;
                cp_cg(sA + soff, A + (size_t)gr * Kp + k0 + u * 8, gr < M ? 16 : 0);
                cp_cg(sB + soff, BT + (size_t)(col0 + row) * Kp + k0 + u * 8, 16);
            }
        }
        CP_COMMIT();
    };
    auto compute = [&](int c) {
        int stage = c % 3;
        uint32_t bA = sb + (uint32_t)stage * 32768u;
        uint32_t bB = bA + 16384u;
#pragma unroll
        for (int ks = 0; ks < 4; ks++) {
            uint32_t a[4][4], b[4][2];
#pragma unroll
            for (int mi = 0; mi < 4; mi++) {
                uint32_t byte = (uint32_t)((wr * 64 + mi * 16 + (lane & 15)) * 128 +
                                           ks * 32 + ((lane >> 4) << 4));
                LDSM_X4(a[mi][0], a[mi][1], a[mi][2], a[mi][3], bA + SMEM_SWZ(byte));
            }
#pragma unroll
            for (int ni = 0; ni < 4; ni++) {
                uint32_t byte = (uint32_t)((wc * 32 + ni * 8 + (lane & 7)) * 128 +
                                           ks * 32 + (((lane >> 3) & 1) << 4));
                LDSM_X2(b[ni][0], b[ni][1], bB + SMEM_SWZ(byte));
            }
#pragma unroll
            for (int mi = 0; mi < 4; mi++)
#pragma unroll
                for (int ni = 0; ni < 4; ni++)
                    MMA16816(acc[mi][ni], a[mi][0], a[mi][1], a[mi][2], a[mi][3],
                             b[ni][0], b[ni][1]);
        }
    };

    issue(0);
    issue(1);
    for (int c = 0; c < nch; c++) {
        asm volatile("cp.async.wait_group 1;" ::: "memory");
        __syncthreads();
        issue(c + 2);
        compute(c);
    }

    float cs[4][2], cq[4][2];
    if (EPI == 3) {
#pragma unroll
        for (int ni = 0; ni < 4; ni++) {
            cs[ni][0] = cs[ni][1] = 0.f;
            cq[ni][0] = cq[ni][1] = 0.f;
        }
    }

#pragma unroll
    for (int mi = 0; mi < 4; mi++) {
#pragma unroll
        for (int ni = 0; ni < 4; ni++) {
            int r = row0 + wr * 64 + mi * 16 + (lane >> 2);
            int c = col0 + wc * 32 + ni * 8 + (lane & 3) * 2;
            float v0 = acc[mi][ni][0], v1 = acc[mi][ni][1];
            float v2 = acc[mi][ni][2], v3 = acc[mi][ni][3];
            if (EPI == 1) {
                float b0 = bias[c], b1 = bias[c + 1];
                v0 = fmaxf(v0 + b0, 0.f); v1 = fmaxf(v1 + b1, 0.f);
                v2 = fmaxf(v2 + b0, 0.f); v3 = fmaxf(v3 + b1, 0.f);
                __nv_bfloat16* P = g_Fpk;
#pragma unroll
                for (int hh = 0; hh < 2; hh++) {
                    int rr = r + hh * 8;
                    if (rr >= M) continue;
                    float u0 = hh ? v2 : v0, u1 = hh ? v3 : v1;
                    size_t base = (size_t)rr * 3072 + c;
                    __nv_bfloat162 hp = __floats2bfloat162_rn(u0, u1);
                    __nv_bfloat162 lp = __floats2bfloat162_rn(
                        u0 - __bfloat162float(hp.x), u1 - __bfloat162float(hp.y));
                    *(__nv_bfloat162*)&P[base]        = hp;
                    *(__nv_bfloat162*)&P[base + 1024] = lp;
                    *(__nv_bfloat162*)&P[base + 2048] = hp;
                }
            } else {
                if (r < M) {
                    C[(size_t)r * Nc + c] = v0;
                    C[(size_t)r * Nc + c + 1] = v1;
                    if (EPI == 2)
                        *(__half2*)(g_xlrh + (size_t)r * 512 + c) = __floats2half2_rn(v0, v1);
                    if (EPI == 3) {
                        cs[ni][0] += v0; cq[ni][0] += v0 * v0;
                        cs[ni][1] += v1; cq[ni][1] += v1 * v1;
                    }
                }
                if (r + 8 < M) {
                    C[(size_t)(r + 8) * Nc + c] = v2;
                    C[(size_t)(r + 8) * Nc + c + 1] = v3;
                    if (EPI == 2)
                        *(__half2*)(g_xlrh + (size_t)(r + 8) * 512 + c) = __floats2half2_rn(v2, v3);
                    if (EPI == 3) {
                        cs[ni][0] += v2; cq[ni][0] += v2 * v2;
                        cs[ni][1] += v3; cq[ni][1] += v3 * v3;
                    }
                }
            }
        }
    }
    if (EPI == 3) {
        __syncthreads();
#pragma unroll
        for (int ni = 0; ni < 4; ni++) {
            int gc = col0 + wc * 32 + ni * 8 + (lane & 3) * 2;
            atomicAdd(&s_st[gc],       cs[ni][0]);
            atomicAdd(&s_st[gc + 1],   cs[ni][1]);
            atomicAdd(&s_st[256 + gc],     cq[ni][0]);
            atomicAdd(&s_st[256 + gc + 1], cq[ni][1]);
        }
        __syncthreads();
        if (tid < 256) {
            atomicAdd(&g_sum[tid],   s_st[tid]);
            atomicAdd(&g_sumsq[tid], s_st[tid + 256]);
        }
    }
}

// ---------------- ee GEMM (Kp=64, x2 pack) fused with GATv2 score ---------------
#define SC_SMEM 55296

__global__ void __launch_bounds__(512, 1) gemm_score(
    const __nv_bfloat16* __restrict__ A, const __nv_bfloat16* __restrict__ BT,
    const float* __restrict__ att,
    const int* __restrict__ src, const int* __restrict__ dst) {
    extern __shared__ char smc[];
    uint32_t sb = smem_u32(smc);
    float* sc_s  = (float*)(smc + 49152);
    float* att_s = (float*)(smc + 53248);
    int*   ss_s  = (int*)(smc + 54272);
    int*   sd_s  = (int*)(smc + 54784);
    int tid = threadIdx.x, lane = tid & 31, w = tid >> 5;
    int wr = w & 3, wc = w >> 2;
    int row0 = blockIdx.x * 128;

    if (blockIdx.x == 0 && tid < 256) { g_sum[tid] = 0.f; g_sumsq[tid] = 0.f; }

    if (tid < 256) att_s[tid] = att[tid];
    if (tid < 128) {
        int e = row0 + tid;
        int s, d;
        if (e < Ee)       { s = src[e]; d = dst[e]; }
        else if (e < ETOT){ s = e - Ee; d = s; }
        else              { s = 0; d = 0; }
        ss_s[tid] = s; sd_s[tid] = d;
    }
#pragma unroll
    for (int p = 0; p < 2; p++) {
        int j = tid + (p << 9);
        int row = j >> 3, u = j & 7;
        uint32_t soff = SMEM_SWZ((uint32_t)(row * 128 + u * 16));
        int gr = row0 + row;
        cp_cg(sb + soff, A + (size_t)gr * 64 + u * 8, gr < ETOT ? 16 : 0);
    }
#pragma unroll
    for (int p = 0; p < 4; p++) {
        int j = tid + (p << 9);
        int row = j >> 3, u = j & 7;
        uint32_t soff = 16384u + SMEM_SWZ((uint32_t)(row * 128 + u * 16));
        cp_cg(sb + soff, BT + (size_t)row * 64 + u * 8, 16);
    }
    CP_COMMIT();
    asm volatile("cp.async.wait_group 0;" ::: "memory");
    __syncthreads();

    float acc[2][8][4];
#pragma unroll
    for (int i = 0; i < 2; i++)
#pragma unroll
        for (int j = 0; j < 8; j++)
#pragma unroll
            for (int q = 0; q < 4; q++) acc[i][j][q] = 0.f;

    uint32_t bA = sb;
    uint32_t bB = sb + 16384u;
#pragma unroll
    for (int ks = 0; ks < 4; ks++) {
        uint32_t a[2][4], b[8][2];
#pragma unroll
        for (int mi = 0; mi < 2; mi++) {
            uint32_t byte = (uint32_t)((wr * 32 + mi * 16 + (lane & 15)) * 128 +
                                       ks * 32 + ((lane >> 4) << 4));
            LDSM_X4(a[mi][0], a[mi][1], a[mi][2], a[mi][3], bA + SMEM_SWZ(byte));
        }
#pragma unroll
        for (int ni = 0; ni < 8; ni++) {
            uint32_t byte = (uint32_t)((wc * 64 + ni * 8 + (lane & 7)) * 128 +
                                       ks * 32 + (((lane >> 3) & 1) << 4));
            LDSM_X2(b[ni][0], b[ni][1], bB + SMEM_SWZ(byte));
        }
#pragma unroll
        for (int mi = 0; mi < 2; mi++)
#pragma unroll
            for (int ni = 0; ni < 8; ni++)
                MMA16816(acc[mi][ni], a[mi][0], a[mi][1], a[mi][2], a[mi][3],
                         b[ni][0], b[ni][1]);
    }

#pragma unroll
    for (int mi = 0; mi < 2; mi++) {
#pragma unroll
        for (int hf = 0; hf < 2; hf++) {
            int r = wr * 32 + mi * 16 + (lane >> 2) + hf * 8;
            int s = ss_s[r], d = sd_s[r];
            const __half* xlp = g_xlrh + (size_t)s * 512;
            const __half* xrp = g_xlrh + (size_t)d * 512 + 256;
            float h0 = 0.f, h1 = 0.f;
#pragma unroll
            for (int ni = 0; ni < 8; ni++) {
                int c0 = wc * 64 + ni * 8 + (lane & 3) * 2;
                float2 xlv = __half22float2(*(const __half2*)(xlp + c0));
                float2 xrv = __half22float2(*(const __half2*)(xrp + c0));
                float z0 = acc[mi][ni][hf * 2 + 0] + xlv.x + xrv.x;
                float z1 = acc[mi][ni][hf * 2 + 1] + xlv.y + xrv.y;
                z0 = (z0 > 0.f) ? z0 : 0.2f * z0;
                z1 = (z1 > 0.f) ? z1 : 0.2f * z1;
                float pp = z0 * att_s[c0] + z1 * att_s[c0 + 1];
                if (ni < 4) h0 += pp; else h1 += pp;
            }
            h0 += __shfl_xor_sync(0xffffffffu, h0, 1);
            h0 += __shfl_xor_sync(0xffffffffu, h0, 2);
            h1 += __shfl_xor_sync(0xffffffffu, h1, 1);
            h1 += __shfl_xor_sync(0xffffffffu, h1, 2);
            if ((lane & 3) == 0) {
                sc_s[r * 8 + wc * 2]     = h0;
                sc_s[r * 8 + wc * 2 + 1] = h1;
            }
        }
    }
    __syncthreads();
#pragma unroll
    for (int p = 0; p < 2; p++) {
        int i = tid + (p << 9);
        int r = i >> 3;
        int e = row0 + r;
        if (e < ETOT) g_sc[(size_t)e * 8 + (i & 7)] = sc_s[i];
    }
}

// ---------------- CSR build ------------------------------------------------------
__global__ void k_zero_icnt() {
    int i = blockIdx.x * blockDim.x + threadIdx.x;
    if (i < Nn) g_icnt[i] = 0;
}
__global__ void k_count(const int* __restrict__ dst) {
    int e = blockIdx.x * blockDim.x + threadIdx.x;
    if (e < Ee) atomicAdd(&g_icnt[dst[e]], 1);
}
__global__ void k_scan() {
    __shared__ int part[1024];
    int t = threadIdx.x;
    const int SEG = (Nn + 1023) / 1024;
    int base = t * SEG;
    int s = 0;
    for (int i = 0; i < SEG; i++) {
        int idx = base + i;
        if (idx < Nn) s += g_icnt[idx];
    }
    part[t] = s;
    __syncthreads();
    for (int off = 1; off < 1024; off <<= 1) {
        int v = (t >= off) ? part[t - off] : 0;
        __syncthreads();
        part[t] += v;
        __syncthreads();
    }
    int run = (t == 0) ? 0 : part[t - 1];
    for (int i = 0; i < SEG; i++) {
        int idx = base + i;
        if (idx < Nn) {
            g_rowptr[idx] = run;
            g_tmp[idx] = run;
            run += g_icnt[idx];
        }
    }
    if (t == 1023) g_rowptr[Nn] = run;
}
__global__ void k_scatter(const int* __restrict__ src, const int* __restrict__ dst) {
    int e = blockIdx.x * blockDim.x + threadIdx.x;
    if (e >= Ee) return;
    int pos = atomicAdd(&g_tmp[dst[e]], 1);
    g_adj[pos] = make_int2(src[e], e);
}
__global__ void k_loop_mean(const float* __restrict__ ew) {
    int d    = blockIdx.x * 8 + (threadIdx.x >> 5);
    int lane = threadIdx.x & 31;
    if (d >= Nn) return;
    int beg = g_rowptr[d], end = g_rowptr[d + 1];
    float s = 0.f;
    for (int i = beg; i < end; i++)
        s += ew[(size_t)g_adj[i].y * EDIMc + lane];
    g_loop[(size_t)d * EDIMc + lane] = s / fmaxf((float)(end - beg), 1.f);
}

// ---------------- per-node softmax + aggregation (warp-coop 4-edge batches) -----
// Lane l cooperatively loads score of edge base+(l>>3), head (l&7); adjacency and
// weights are then shuffle-broadcast so the gather loop issues 8 independent
// float4 loads per batch (no serialized adj->score->gather chain).
__global__ void k_node() {
    __shared__ float s_st[512];
    int tid  = threadIdx.x;
    int d    = blockIdx.x * 8 + (tid >> 5);
    int lane = tid & 31;
    s_st[tid] = 0.f;
    s_st[tid + 256] = 0.f;
    __syncthreads();

    int beg = g_rowptr[d], end = g_rowptr[d + 1];
    const float* ssc = g_sc + (size_t)(Ee + d) * Hh;

    int hh = lane >> 2;
    int c0 = lane << 3;

    float den;
    float acc[8];
    {
        float a = __expf(ssc[hh]);
        den = a;
        const float4* xp = (const float4*)(g_xlr + (size_t)d * 512 + c0);
        float4 u0 = xp[0], u1 = xp[1];
        acc[0] = a * u0.x; acc[1] = a * u0.y; acc[2] = a * u0.z; acc[3] = a * u0.w;
        acc[4] = a * u1.x; acc[5] = a * u1.y; acc[6] = a * u1.z; acc[7] = a * u1.w;
    }
    for (int base = beg; base < end; base += 4) {
        int ei = base + (lane >> 3);          // 8 lanes per edge slot
        float s_l = -1e30f;                   // __expf -> 0 for padding slots
        int   src_l = d;                      // safe gather address
        if (ei < end) {
            int2 se = g_adj[ei];
            src_l = se.x;
            s_l = g_sc[(size_t)se.y * Hh + (lane & 7)];
        }
#pragma unroll
        for (int j = 0; j < 4; j++) {
            float w = __expf(__shfl_sync(0xffffffffu, s_l, (j << 3) + hh));
            int   s = __shfl_sync(0xffffffffu, src_l, j << 3);
            const float4* xp = (const float4*)(g_xlr + (size_t)s * 512 + c0);
            float4 u0 = xp[0], u1 = xp[1];
            den += w;
            acc[0] += w * u0.x; acc[1] += w * u0.y; acc[2] += w * u0.z; acc[3] += w * u0.w;
            acc[4] += w * u1.x; acc[5] += w * u1.y; acc[6] += w * u1.z; acc[7] += w * u1.w;
        }
    }
    float inv = 1.f / den;
#pragma unroll
    for (int q = 0; q < 8; q++) acc[q] *= inv;

    float4* op = (float4*)(g_agg + (size_t)d * DIMc + c0);
    op[0] = make_float4(acc[0], acc[1], acc[2], acc[3]);
    op[1] = make_float4(acc[4], acc[5], acc[6], acc[7]);

#pragma unroll
    for (int q = 0; q < 8; q++) {
        atomicAdd(&s_st[c0 + q], acc[q]);
        atomicAdd(&s_st[256 + c0 + q], acc[q] * acc[q]);
    }
    __syncthreads();
    if (tid < 256) {
        atomicAdd(&g_sum[tid], s_st[tid]);
        atomicAdd(&g_sumsq[tid], s_st[tid + 256]);
    }
}

// ---------------- BatchNorm apply -------------------------------------------------
template<bool PACK>
__global__ void k_bnapply(const float* __restrict__ X, const float* __restrict__ gam,
                          const float* __restrict__ bet, const float* __restrict__ res,
                          float* __restrict__ out) {
    int i = blockIdx.x * blockDim.x + threadIdx.x;
    if (i >= Nn * DIMc) return;
    int c = i & (DIMc - 1);
    float mu  = g_sum[c]   * (1.f / Nn);
    float var = g_sumsq[c] * (1.f / Nn) - mu * mu;
    float y = (X[i] - mu) * rsqrtf(var + 1e-5f) * gam[c] + bet[c];
    y = (y > 0.f) ? y : 0.01f * y;
    float v = res[i] + y;
    out[i] = v;
    if (PACK) {
        int r = i >> 8;
        __nv_bfloat16 h = __float2bfloat16(v);
        size_t b = (size_t)r * 768 + c;
        g_Apk[b]       = h;
        g_Apk[b + 256] = __float2bfloat16(v - __bfloat162float(h));
        g_Apk[b + 512] = h;
    }
}

// ---------------- host orchestration ----------------------------------------------
static inline int cdiv(int a, int b) { return (a + b - 1) / b; }

extern "C" void kernel_launch(void* const* d_in, const int* in_sizes, int n_in,
                              void* d_out, int out_size) {
    const float* nf    = (const float*)d_in[0];
    const int*   ei    = (const int*)  d_in[1];
    const float* ew    = (const float*)d_in[2];
    const float* g1_Wl = (const float*)d_in[3];
    const float* g1_Wr = (const float*)d_in[4];
    const float* g1_We = (const float*)d_in[5];
    const float* g1_at = (const float*)d_in[6];
    const float* g2_Wl = (const float*)d_in[8];
    const float* g2_Wr = (const float*)d_in[9];
    const float* g2_We = (const float*)d_in[10];
    const float* g2_at = (const float*)d_in[11];
    const float* n1_g  = (const float*)d_in[13];
    const float* n1_b  = (const float*)d_in[14];
    const float* n2_g  = (const float*)d_in[15];
    const float* n2_b  = (const float*)d_in[16];
    const float* n3_g  = (const float*)d_in[17];
    const float* n3_b  = (const float*)d_in[18];
    const float* ff_W1 = (const float*)d_in[19];
    const float* ff_b1 = (const float*)d_in[20];
    const float* ff_W2 = (const float*)d_in[21];
    const int* src = ei;
    const int* dst = ei + Ee;
    float* out = (float*)d_out;

    void* p;
    cudaGetSymbolAddress(&p, g_xlr);  float* xlr  = (float*)p;
    cudaGetSymbolAddress(&p, g_agg);  float* agg  = (float*)p;
    cudaGetSymbolAddress(&p, g_h1);   float* h1   = (float*)p;
    cudaGetSymbolAddress(&p, g_h2);   float* h2   = (float*)p;
    cudaGetSymbolAddress(&p, g_ff2);  float* ff2  = (float*)p;
    cudaGetSymbolAddress(&p, g_Apk);  __nv_bfloat16* Apk = (__nv_bfloat16*)p;
    cudaGetSymbolAddress(&p, g_Fpk);  __nv_bfloat16* Fpk = (__nv_bfloat16*)p;
    cudaGetSymbolAddress(&p, g_EApk); __nv_bfloat16* EApk = (__nv_bfloat16*)p;
    cudaGetSymbolAddress(&p, g_Wpk);  __nv_bfloat16* Wpk = (__nv_bfloat16*)p;

    cudaFuncSetAttribute(gemm_pk<0>, cudaFuncAttributeMaxDynamicSharedMemorySize, GEMM_SMEM_PK);
    cudaFuncSetAttribute(gemm_pk<1>, cudaFuncAttributeMaxDynamicSharedMemorySize, GEMM_SMEM_PK);
    cudaFuncSetAttribute(gemm_pk<2>, cudaFuncAttributeMaxDynamicSharedMemorySize, GEMM_SMEM_PK);
    cudaFuncSetAttribute(gemm_pk<3>, cudaFuncAttributeMaxDynamicSharedMemorySize, GEMM_SMEM_PK);
    cudaFuncSetAttribute(gemm_score, cudaFuncAttributeMaxDynamicSharedMemorySize, SC_SMEM);

    cudaStream_t sd = 0;
    cudaEvent_t ev0 = nullptr, ev1 = nullptr;
    cudaStreamCreateWithFlags(&sd, cudaStreamNonBlocking);
    cudaEventCreateWithFlags(&ev0, cudaEventDisableTiming);
    cudaEventCreateWithFlags(&ev1, cudaEventDisableTiming);

    // ---- fork: CSR + edge-attr chain on side stream ----
    cudaEventRecord(ev0, 0);
    cudaStreamWaitEvent(sd, ev0, 0);
    k_zero_icnt<<<cdiv(Nn, 256), 256, 0, sd>>>();
    k_count<<<cdiv(Ee, 256), 256, 0, sd>>>(dst);
    k_scan<<<1, 1024, 0, sd>>>();
    k_scatter<<<cdiv(Ee, 256), 256, 0, sd>>>(src, dst);
    k_loop_mean<<<cdiv(Nn, 8), 256, 0, sd>>>(ew);
    k_pack_ea<<<cdiv(ETOT * EDIMc, 256), 256, 0, sd>>>(ew);
    cudaEventRecord(ev1, sd);

    // ---- main stream: weight packs, node pack, xlr GEMM ----
    k_packT_all<<<cdiv(802816, 256), 256>>>(g1_Wl, g1_Wr, g1_We, g2_Wl, g2_Wr, g2_We,
                                            ff_W1, ff_W2, Wpk);
    k_pack_node<<<cdiv(Nn * DIMc, 256), 256>>>(nf, Apk, Nn, DIMc);

    dim3 gXLR(4, cdiv(Nn, 128));
    int nbScore = cdiv(ETOT, 128);
    int nbNode  = cdiv(Nn, 8);

    gemm_pk<2><<<gXLR, 256, GEMM_SMEM_PK>>>(Apk, Wpk + OWLR1, nullptr, xlr, Nn, 768, 512);

    // ---- join ----
    cudaStreamWaitEvent(0, ev1, 0);

    // ---- block 1 ----
    gemm_score<<<nbScore, 512, SC_SMEM>>>(EApk, Wpk + OWE1, g1_at, src, dst);
    k_node<<<nbNode, 256>>>();
    k_bnapply<true><<<cdiv(Nn * DIMc, 256), 256>>>(agg, n1_g, n1_b, nf, h1);

    // ---- block 2 ----
    gemm_pk<2><<<gXLR, 256, GEMM_SMEM_PK>>>(Apk, Wpk + OWLR2, nullptr, xlr, Nn, 768, 512);
    gemm_score<<<nbScore, 512, SC_SMEM>>>(EApk, Wpk + OWE2, g2_at, src, dst);
    k_node<<<nbNode, 256>>>();
    k_bnapply<true><<<cdiv(Nn * DIMc, 256), 256>>>(agg, n2_g, n2_b, h1, h2);

    // ---- feed-forward ----
    dim3 gF1(8, cdiv(Nn, 128));
    gemm_pk<1><<<gF1, 256, GEMM_SMEM_PK>>>(Apk, Wpk + OW1, ff_b1, nullptr, Nn, 768, DFFc);
    dim3 gF2(2, cdiv(Nn, 128));
    gemm_pk<3><<<gF2, 256, GEMM_SMEM_PK>>>(Fpk, Wpk + OW2, nullptr, ff2, Nn, 3072, DIMc);
    k_bnapply<false><<<cdiv(Nn * DIMc, 256), 256>>>(ff2, n3_g, n3_b, h2, out);
}

// round 14
// speedup vs baseline: 1.0276x; 1.0276x over previous
#include <cuda_runtime.h>
#include <cuda_bf16.h>
#include <cuda_fp16.h>
#include <math.h>
#include <stdint.h>

#define Nn    20000
#define Ee    320000
#define DIMc  256
#define Hh    8
#define EDIMc 32
#define DFFc  1024
#define ETOT  (Ee + Nn)

// ---------------- scratch (device globals) -----------------------------------
static __device__ float    g_xlr[(size_t)Nn * 512];
static __device__ __half   g_xlrh[(size_t)Nn * 512];
static __device__ float    g_loop[(size_t)Nn * EDIMc];
static __device__ int      g_icnt[Nn];
static __device__ float    g_sc [(size_t)ETOT * Hh];
static __device__ float    g_agg[(size_t)Nn * DIMc];
static __device__ float    g_h1 [(size_t)Nn * DIMc];
static __device__ float    g_h2 [(size_t)Nn * DIMc];
static __device__ float    g_ff2[(size_t)Nn * DIMc];
static __device__ float    g_sum[DIMc];
static __device__ float    g_sumsq[DIMc];
static __device__ int      g_rowptr[Nn + 1];
static __device__ int      g_tmp[Nn];
static __device__ int2     g_adj[Ee];

static __device__ __nv_bfloat16 g_Apk[(size_t)Nn * 768];
static __device__ __nv_bfloat16 g_Fpk[(size_t)Nn * 3072];
static __device__ __nv_bfloat16 g_EApk[(size_t)ETOT * 64];   // [Ah|Al], Kp=64
#define OWLR1 0
#define OWE1  393216
#define OWLR2 409600
#define OWE2  802816
#define OW1   819200
#define OW2   1605632
#define WPK_TOTAL 2392064
static __device__ __nv_bfloat16 g_Wpk[WPK_TOTAL];

// ---------------- PTX helpers --------------------------------------------------
__device__ __forceinline__ uint32_t smem_u32(const void* p) {
    uint32_t a;
    asm("{ .reg .u64 t; cvta.to.shared.u64 t, %1; cvt.u32.u64 %0, t; }"
        : "=r"(a) : "l"(p));
    return a;
}
#define LDSM_X4(r0, r1, r2, r3, addr) \
    asm volatile("ldmatrix.sync.aligned.m8n8.x4.shared.b16 {%0,%1,%2,%3}, [%4];" \
                 : "=r"(r0), "=r"(r1), "=r"(r2), "=r"(r3) : "r"(addr))
#define LDSM_X2(r0, r1, addr) \
    asm volatile("ldmatrix.sync.aligned.m8n8.x2.shared.b16 {%0,%1}, [%2];" \
                 : "=r"(r0), "=r"(r1) : "r"(addr))
#define MMA16816(c, a0, a1, a2, a3, b0, b1) \
    asm volatile("mma.sync.aligned.m16n8k16.row.col.f32.bf16.bf16.f32 " \
                 "{%0,%1,%2,%3}, {%4,%5,%6,%7}, {%8,%9}, {%0,%1,%2,%3};" \
                 : "+f"((c)[0]), "+f"((c)[1]), "+f"((c)[2]), "+f"((c)[3]) \
                 : "r"(a0), "r"(a1), "r"(a2), "r"(a3), "r"(b0), "r"(b1))
__device__ __forceinline__ void cp_cg(uint32_t dst, const void* src, int sz) {
    asm volatile("cp.async.cg.shared.global [%0], [%1], 16, %2;"
                 :: "r"(dst), "l"(src), "r"(sz));
}
#define CP_COMMIT() asm volatile("cp.async.commit_group;" ::: "memory")
#define SMEM_SWZ(b) ((b) ^ (((b) >> 3) & 0x70))

// ---------------- pack kernels --------------------------------------------------
__global__ void k_pack_node(const float* __restrict__ X, __nv_bfloat16* __restrict__ A,
                            int rows, int K) {
    int i = blockIdx.x * blockDim.x + threadIdx.x;
    if (i >= rows * K) return;
    int r = i / K, k = i - r * K;
    float v = X[i];
    __nv_bfloat16 h = __float2bfloat16(v);
    __nv_bfloat16 l = __float2bfloat16(v - __bfloat162float(h));
    size_t b = (size_t)r * (3 * K);
    A[b + k] = h;
    A[b + K + k] = l;
    A[b + 2 * K + k] = h;
}
__global__ void k_pack_ea(const float* __restrict__ ew) {
    int i = blockIdx.x * blockDim.x + threadIdx.x;
    if (i >= ETOT * EDIMc) return;
    int r = i >> 5, k = i & 31;
    float v = (r < Ee) ? ew[i] : g_loop[(size_t)(r - Ee) * EDIMc + k];
    __nv_bfloat16 h = __float2bfloat16(v);
    __nv_bfloat16 l = __float2bfloat16(v - __bfloat162float(h));
    size_t b = (size_t)r * 64;
    g_EApk[b + k]      = h;
    g_EApk[b + 32 + k] = l;
}
__device__ __forceinline__ void pack_w_one(const float* __restrict__ W,
                                           __nv_bfloat16* __restrict__ WT,
                                           int i, int K, int N, int Kp) {
    int k = i / N, n = i - k * N;
    float v = W[i];
    __nv_bfloat16 h = __float2bfloat16(v);
    __nv_bfloat16 l = __float2bfloat16(v - __bfloat162float(h));
    size_t b = (size_t)n * Kp;
    WT[b + k]         = h;
    WT[b + K + k]     = h;
    WT[b + 2 * K + k] = l;
    if (k < Kp - 3 * K) WT[b + 3 * K + k] = __float2bfloat16(0.f);
}
__device__ __forceinline__ void pack_w_x2(const float* __restrict__ W,
                                          __nv_bfloat16* __restrict__ WT, int i) {
    int k = i >> 8, n = i & 255;
    __nv_bfloat16 h = __float2bfloat16(W[i]);
    WT[n * 64 + k]      = h;
    WT[n * 64 + 32 + k] = h;
}
__global__ void k_packT_all(const float* w0, const float* w1, const float* w2,
                            const float* w3, const float* w4, const float* w5,
                            const float* w6, const float* w7,
                            __nv_bfloat16* __restrict__ WT) {
    int i = blockIdx.x * blockDim.x + threadIdx.x;
    if (i < 65536)        pack_w_one(w0, WT + OWLR1,          i,           DIMc, DIMc, 768);
    else if (i < 131072)  pack_w_one(w1, WT + OWLR1 + 196608, i - 65536,   DIMc, DIMc, 768);
    else if (i < 139264)  pack_w_x2 (w2, WT + OWE1,           i - 131072);
    else if (i < 204800)  pack_w_one(w3, WT + OWLR2,          i - 139264,  DIMc, DIMc, 768);
    else if (i < 270336)  pack_w_one(w4, WT + OWLR2 + 196608, i - 204800,  DIMc, DIMc, 768);
    else if (i < 278528)  pack_w_x2 (w5, WT + OWE2,           i - 270336);
    else if (i < 540672)  pack_w_one(w6, WT + OW1,            i - 278528,  DIMc, DFFc, 768);
    else if (i < 802816)  pack_w_one(w7, WT + OW2,            i - 540672,  DFFc, DIMc, 3072);
}

// ---------------- 3-stage pipelined bf16 GEMM (K-packed x3) --------------------
#define GEMM_SMEM_PK 98304

template<int EPI>
__global__ void __launch_bounds__(256, 2) gemm_pk(
    const __nv_bfloat16* __restrict__ A, const __nv_bfloat16* __restrict__ BT,
    const float* __restrict__ bias, float* __restrict__ C,
    int M, int Kp, int Nc) {
    extern __shared__ __nv_bfloat16 sm[];
    __shared__ float s_st[512];
    uint32_t sb = smem_u32(sm);
    int tid  = threadIdx.x;
    int lane = tid & 31;
    int w    = tid >> 5;
    int wr   = w & 1;
    int wc   = w >> 1;
    int row0 = blockIdx.y * 128;
    int col0 = blockIdx.x * 128;

    if (EPI == 1 && blockIdx.x == 0 && blockIdx.y == 0 && tid < 256) {
        g_sum[tid] = 0.f; g_sumsq[tid] = 0.f;
    }
    if (EPI == 3) { s_st[tid] = 0.f; s_st[tid + 256] = 0.f; }

    float acc[4][4][4];
#pragma unroll
    for (int i = 0; i < 4; i++)
#pragma unroll
        for (int j = 0; j < 4; j++)
#pragma unroll
            for (int q = 0; q < 4; q++) acc[i][j][q] = 0.f;

    const int nch = Kp >> 6;

    auto issue = [&](int c) {
        if (c < nch) {
            int stage = c % 3;
            uint32_t sA = sb + (uint32_t)stage * 32768u;
            uint32_t sB = sA + 16384u;
            int k0 = c << 6;
#pragma unroll
            for (int p = 0; p < 4; p++) {
                int idx = tid + (p << 8);
                int row = idx >> 3, u = idx & 7;
                uint32_t soff = SMEM_SWZ((uint32_t)(row * 128 + u * 16));
                int gr = row0 + row;
                cp_cg(sA + soff, A + (size_t)gr * Kp + k0 + u * 8, gr < M ? 16 : 0);
                cp_cg(sB + soff, BT + (size_t)(col0 + row) * Kp + k0 + u * 8, 16);
            }
        }
        CP_COMMIT();
    };
    auto compute = [&](int c) {
        int stage = c % 3;
        uint32_t bA = sb + (uint32_t)stage * 32768u;
        uint32_t bB = bA + 16384u;
#pragma unroll
        for (int ks = 0; ks < 4; ks++) {
            uint32_t a[4][4], b[4][2];
#pragma unroll
            for (int mi = 0; mi < 4; mi++) {
                uint32_t byte = (uint32_t)((wr * 64 + mi * 16 + (lane & 15)) * 128 +
                                           ks * 32 + ((lane >> 4) << 4));
                LDSM_X4(a[mi][0], a[mi][1], a[mi][2], a[mi][3], bA + SMEM_SWZ(byte));
            }
#pragma unroll
            for (int ni = 0; ni < 4; ni++) {
                uint32_t byte = (uint32_t)((wc * 32 + ni * 8 + (lane & 7)) * 128 +
                                           ks * 32 + (((lane >> 3) & 1) << 4));
                LDSM_X2(b[ni][0], b[ni][1], bB + SMEM_SWZ(byte));
            }
#pragma unroll
            for (int mi = 0; mi < 4; mi++)
#pragma unroll
                for (int ni = 0; ni < 4; ni++)
                    MMA16816(acc[mi][ni], a[mi][0], a[mi][1], a[mi][2], a[mi][3],
                             b[ni][0], b[ni][1]);
        }
    };

    issue(0);
    issue(1);
    for (int c = 0; c < nch; c++) {
        asm volatile("cp.async.wait_group 1;" ::: "memory");
        __syncthreads();
        issue(c + 2);
        compute(c);
    }

    float cs[4][2], cq[4][2];
    if (EPI == 3) {
#pragma unroll
        for (int ni = 0; ni < 4; ni++) {
            cs[ni][0] = cs[ni][1] = 0.f;
            cq[ni][0] = cq[ni][1] = 0.f;
        }
    }

#pragma unroll
    for (int mi = 0; mi < 4; mi++) {
#pragma unroll
        for (int ni = 0; ni < 4; ni++) {
            int r = row0 + wr * 64 + mi * 16 + (lane >> 2);
            int c = col0 + wc * 32 + ni * 8 + (lane & 3) * 2;
            float v0 = acc[mi][ni][0], v1 = acc[mi][ni][1];
            float v2 = acc[mi][ni][2], v3 = acc[mi][ni][3];
            if (EPI == 1) {
                float b0 = bias[c], b1 = bias[c + 1];
                v0 = fmaxf(v0 + b0, 0.f); v1 = fmaxf(v1 + b1, 0.f);
                v2 = fmaxf(v2 + b0, 0.f); v3 = fmaxf(v3 + b1, 0.f);
                __nv_bfloat16* P = g_Fpk;
#pragma unroll
                for (int hh = 0; hh < 2; hh++) {
                    int rr = r + hh * 8;
                    if (rr >= M) continue;
                    float u0 = hh ? v2 : v0, u1 = hh ? v3 : v1;
                    size_t base = (size_t)rr * 3072 + c;
                    __nv_bfloat162 hp = __floats2bfloat162_rn(u0, u1);
                    __nv_bfloat162 lp = __floats2bfloat162_rn(
                        u0 - __bfloat162float(hp.x), u1 - __bfloat162float(hp.y));
                    *(__nv_bfloat162*)&P[base]        = hp;
                    *(__nv_bfloat162*)&P[base + 1024] = lp;
                    *(__nv_bfloat162*)&P[base + 2048] = hp;
                }
            } else {
                if (r < M) {
                    C[(size_t)r * Nc + c] = v0;
                    C[(size_t)r * Nc + c + 1] = v1;
                    if (EPI == 2)
                        *(__half2*)(g_xlrh + (size_t)r * 512 + c) = __floats2half2_rn(v0, v1);
                    if (EPI == 3) {
                        cs[ni][0] += v0; cq[ni][0] += v0 * v0;
                        cs[ni][1] += v1; cq[ni][1] += v1 * v1;
                    }
                }
                if (r + 8 < M) {
                    C[(size_t)(r + 8) * Nc + c] = v2;
                    C[(size_t)(r + 8) * Nc + c + 1] = v3;
                    if (EPI == 2)
                        *(__half2*)(g_xlrh + (size_t)(r + 8) * 512 + c) = __floats2half2_rn(v2, v3);
                    if (EPI == 3) {
                        cs[ni][0] += v2; cq[ni][0] += v2 * v2;
                        cs[ni][1] += v3; cq[ni][1] += v3 * v3;
                    }
                }
            }
        }
    }
    if (EPI == 3) {
        __syncthreads();
#pragma unroll
        for (int ni = 0; ni < 4; ni++) {
            int gc = col0 + wc * 32 + ni * 8 + (lane & 3) * 2;
            atomicAdd(&s_st[gc],       cs[ni][0]);
            atomicAdd(&s_st[gc + 1],   cs[ni][1]);
            atomicAdd(&s_st[256 + gc],     cq[ni][0]);
            atomicAdd(&s_st[256 + gc + 1], cq[ni][1]);
        }
        __syncthreads();
        if (tid < 256) {
            atomicAdd(&g_sum[tid],   s_st[tid]);
            atomicAdd(&g_sumsq[tid], s_st[tid + 256]);
        }
    }
}

// ---------------- ee GEMM (Kp=64, x2 pack) fused with GATv2 score ---------------
#define SC_SMEM 55296

__global__ void __launch_bounds__(512, 1) gemm_score(
    const __nv_bfloat16* __restrict__ A, const __nv_bfloat16* __restrict__ BT,
    const float* __restrict__ att,
    const int* __restrict__ src, const int* __restrict__ dst) {
    extern __shared__ char smc[];
    uint32_t sb = smem_u32(smc);
    float* sc_s  = (float*)(smc + 49152);
    float* att_s = (float*)(smc + 53248);
    int*   ss_s  = (int*)(smc + 54272);
    int*   sd_s  = (int*)(smc + 54784);
    int tid = threadIdx.x, lane = tid & 31, w = tid >> 5;
    int wr = w & 3, wc = w >> 2;
    int row0 = blockIdx.x * 128;

    if (blockIdx.x == 0 && tid < 256) { g_sum[tid] = 0.f; g_sumsq[tid] = 0.f; }

    if (tid < 256) att_s[tid] = att[tid];
    if (tid < 128) {
        int e = row0 + tid;
        int s, d;
        if (e < Ee)       { s = src[e]; d = dst[e]; }
        else if (e < ETOT){ s = e - Ee; d = s; }
        else              { s = 0; d = 0; }
        ss_s[tid] = s; sd_s[tid] = d;
    }
#pragma unroll
    for (int p = 0; p < 2; p++) {
        int j = tid + (p << 9);
        int row = j >> 3, u = j & 7;
        uint32_t soff = SMEM_SWZ((uint32_t)(row * 128 + u * 16));
        int gr = row0 + row;
        cp_cg(sb + soff, A + (size_t)gr * 64 + u * 8, gr < ETOT ? 16 : 0);
    }
#pragma unroll
    for (int p = 0; p < 4; p++) {
        int j = tid + (p << 9);
        int row = j >> 3, u = j & 7;
        uint32_t soff = 16384u + SMEM_SWZ((uint32_t)(row * 128 + u * 16));
        cp_cg(sb + soff, BT + (size_t)row * 64 + u * 8, 16);
    }
    CP_COMMIT();
    asm volatile("cp.async.wait_group 0;" ::: "memory");
    __syncthreads();

    float acc[2][8][4];
#pragma unroll
    for (int i = 0; i < 2; i++)
#pragma unroll
        for (int j = 0; j < 8; j++)
#pragma unroll
            for (int q = 0; q < 4; q++) acc[i][j][q] = 0.f;

    uint32_t bA = sb;
    uint32_t bB = sb + 16384u;
#pragma unroll
    for (int ks = 0; ks < 4; ks++) {
        uint32_t a[2][4], b[8][2];
#pragma unroll
        for (int mi = 0; mi < 2; mi++) {
            uint32_t byte = (uint32_t)((wr * 32 + mi * 16 + (lane & 15)) * 128 +
                                       ks * 32 + ((lane >> 4) << 4));
            LDSM_X4(a[mi][0], a[mi][1], a[mi][2], a[mi][3], bA + SMEM_SWZ(byte));
        }
#pragma unroll
        for (int ni = 0; ni < 8; ni++) {
            uint32_t byte = (uint32_t)((wc * 64 + ni * 8 + (lane & 7)) * 128 +
                                       ks * 32 + (((lane >> 3) & 1) << 4));
            LDSM_X2(b[ni][0], b[ni][1], bB + SMEM_SWZ(byte));
        }
#pragma unroll
        for (int mi = 0; mi < 2; mi++)
#pragma unroll
            for (int ni = 0; ni < 8; ni++)
                MMA16816(acc[mi][ni], a[mi][0], a[mi][1], a[mi][2], a[mi][3],
                         b[ni][0], b[ni][1]);
    }

#pragma unroll
    for (int mi = 0; mi < 2; mi++) {
#pragma unroll
        for (int hf = 0; hf < 2; hf++) {
            int r = wr * 32 + mi * 16 + (lane >> 2) + hf * 8;
            int s = ss_s[r], d = sd_s[r];
            const __half* xlp = g_xlrh + (size_t)s * 512;
            const __half* xrp = g_xlrh + (size_t)d * 512 + 256;
            float h0 = 0.f, h1 = 0.f;
#pragma unroll
            for (int ni = 0; ni < 8; ni++) {
                int c0 = wc * 64 + ni * 8 + (lane & 3) * 2;
                float2 xlv = __half22float2(*(const __half2*)(xlp + c0));
                float2 xrv = __half22float2(*(const __half2*)(xrp + c0));
                float z0 = acc[mi][ni][hf * 2 + 0] + xlv.x + xrv.x;
                float z1 = acc[mi][ni][hf * 2 + 1] + xlv.y + xrv.y;
                z0 = (z0 > 0.f) ? z0 : 0.2f * z0;
                z1 = (z1 > 0.f) ? z1 : 0.2f * z1;
                float pp = z0 * att_s[c0] + z1 * att_s[c0 + 1];
                if (ni < 4) h0 += pp; else h1 += pp;
            }
            h0 += __shfl_xor_sync(0xffffffffu, h0, 1);
            h0 += __shfl_xor_sync(0xffffffffu, h0, 2);
            h1 += __shfl_xor_sync(0xffffffffu, h1, 1);
            h1 += __shfl_xor_sync(0xffffffffu, h1, 2);
            if ((lane & 3) == 0) {
                sc_s[r * 8 + wc * 2]     = h0;
                sc_s[r * 8 + wc * 2 + 1] = h1;
            }
        }
    }
    __syncthreads();
#pragma unroll
    for (int p = 0; p < 2; p++) {
        int i = tid + (p << 9);
        int r = i >> 3;
        int e = row0 + r;
        if (e < ETOT) g_sc[(size_t)e * 8 + (i & 7)] = sc_s[i];
    }
}

// ---------------- CSR build ------------------------------------------------------
__global__ void k_zero_icnt() {
    int i = blockIdx.x * blockDim.x + threadIdx.x;
    if (i < Nn) g_icnt[i] = 0;
}
__global__ void k_count(const int* __restrict__ dst) {
    int e = blockIdx.x * blockDim.x + threadIdx.x;
    if (e < Ee) atomicAdd(&g_icnt[dst[e]], 1);
}
__global__ void k_scan() {
    __shared__ int part[1024];
    int t = threadIdx.x;
    const int SEG = (Nn + 1023) / 1024;
    int base = t * SEG;
    int s = 0;
    for (int i = 0; i < SEG; i++) {
        int idx = base + i;
        if (idx < Nn) s += g_icnt[idx];
    }
    part[t] = s;
    __syncthreads();
    for (int off = 1; off < 1024; off <<= 1) {
        int v = (t >= off) ? part[t - off] : 0;
        __syncthreads();
        part[t] += v;
        __syncthreads();
    }
    int run = (t == 0) ? 0 : part[t - 1];
    for (int i = 0; i < SEG; i++) {
        int idx = base + i;
        if (idx < Nn) {
            g_rowptr[idx] = run;
            g_tmp[idx] = run;
            run += g_icnt[idx];
        }
    }
    if (t == 1023) g_rowptr[Nn] = run;
}
__global__ void k_scatter(const int* __restrict__ src, const int* __restrict__ dst) {
    int e = blockIdx.x * blockDim.x + threadIdx.x;
    if (e >= Ee) return;
    int pos = atomicAdd(&g_tmp[dst[e]], 1);
    g_adj[pos] = make_int2(src[e], e);
}
__global__ void k_loop_mean(const float* __restrict__ ew) {
    int d    = blockIdx.x * 8 + (threadIdx.x >> 5);
    int lane = threadIdx.x & 31;
    if (d >= Nn) return;
    int beg = g_rowptr[d], end = g_rowptr[d + 1];
    float s = 0.f;
    for (int i = beg; i < end; i++)
        s += ew[(size_t)g_adj[i].y * EDIMc + lane];
    g_loop[(size_t)d * EDIMc + lane] = s / fmaxf((float)(end - beg), 1.f);
}

// ---------------- per-node softmax + aggregation (fp16 gather, 2-way unroll) ----
__device__ __forceinline__ void acc_h8(float* acc, const __half* xp, float w) {
    uint4 raw = *(const uint4*)xp;            // 8 halves = 16B
    const __half2* hp = (const __half2*)&raw;
    float2 f0 = __half22float2(hp[0]);
    float2 f1 = __half22float2(hp[1]);
    float2 f2 = __half22float2(hp[2]);
    float2 f3 = __half22float2(hp[3]);
    acc[0] += w * f0.x; acc[1] += w * f0.y;
    acc[2] += w * f1.x; acc[3] += w * f1.y;
    acc[4] += w * f2.x; acc[5] += w * f2.y;
    acc[6] += w * f3.x; acc[7] += w * f3.y;
}
__global__ void k_node() {
    __shared__ float s_st[512];
    int tid  = threadIdx.x;
    int d    = blockIdx.x * 8 + (tid >> 5);
    int lane = tid & 31;
    s_st[tid] = 0.f;
    s_st[tid + 256] = 0.f;
    __syncthreads();

    int beg = g_rowptr[d], end = g_rowptr[d + 1];
    const float* ssc = g_sc + (size_t)(Ee + d) * Hh;

    int hh = lane >> 2;
    int c0 = lane << 3;

    float den;
    float acc[8];
#pragma unroll
    for (int q = 0; q < 8; q++) acc[q] = 0.f;
    {
        float a = __expf(ssc[hh]);
        den = a;
        acc_h8(acc, g_xlrh + (size_t)d * 512 + c0, a);
    }
    int i = beg;
    for (; i + 1 < end; i += 2) {
        int2 e0 = g_adj[i], e1 = g_adj[i + 1];
        float s0 = g_sc[(size_t)e0.y * Hh + hh];
        float s1 = g_sc[(size_t)e1.y * Hh + hh];
        float w0 = __expf(s0), w1 = __expf(s1);
        den += w0 + w1;
        acc_h8(acc, g_xlrh + (size_t)e0.x * 512 + c0, w0);
        acc_h8(acc, g_xlrh + (size_t)e1.x * 512 + c0, w1);
    }
    if (i < end) {
        int2 e0 = g_adj[i];
        float w0 = __expf(g_sc[(size_t)e0.y * Hh + hh]);
        den += w0;
        acc_h8(acc, g_xlrh + (size_t)e0.x * 512 + c0, w0);
    }
    float inv = 1.f / den;
#pragma unroll
    for (int q = 0; q < 8; q++) acc[q] *= inv;

    float4* op = (float4*)(g_agg + (size_t)d * DIMc + c0);
    op[0] = make_float4(acc[0], acc[1], acc[2], acc[3]);
    op[1] = make_float4(acc[4], acc[5], acc[6], acc[7]);

#pragma unroll
    for (int q = 0; q < 8; q++) {
        atomicAdd(&s_st[c0 + q], acc[q]);
        atomicAdd(&s_st[256 + c0 + q], acc[q] * acc[q]);
    }
    __syncthreads();
    if (tid < 256) {
        atomicAdd(&g_sum[tid], s_st[tid]);
        atomicAdd(&g_sumsq[tid], s_st[tid + 256]);
    }
}

// ---------------- BatchNorm apply -------------------------------------------------
template<bool PACK>
__global__ void k_bnapply(const float* __restrict__ X, const float* __restrict__ gam,
                          const float* __restrict__ bet, const float* __restrict__ res,
                          float* __restrict__ out) {
    int i = blockIdx.x * blockDim.x + threadIdx.x;
    if (i >= Nn * DIMc) return;
    int c = i & (DIMc - 1);
    float mu  = g_sum[c]   * (1.f / Nn);
    float var = g_sumsq[c] * (1.f / Nn) - mu * mu;
    float y = (X[i] - mu) * rsqrtf(var + 1e-5f) * gam[c] + bet[c];
    y = (y > 0.f) ? y : 0.01f * y;
    float v = res[i] + y;
    out[i] = v;
    if (PACK) {
        int r = i >> 8;
        __nv_bfloat16 h = __float2bfloat16(v);
        size_t b = (size_t)r * 768 + c;
        g_Apk[b]       = h;
        g_Apk[b + 256] = __float2bfloat16(v - __bfloat162float(h));
        g_Apk[b + 512] = h;
    }
}

// ---------------- host orchestration ----------------------------------------------
static inline int cdiv(int a, int b) { return (a + b - 1) / b; }

extern "C" void kernel_launch(void* const* d_in, const int* in_sizes, int n_in,
                              void* d_out, int out_size) {
    const float* nf    = (const float*)d_in[0];
    const int*   ei    = (const int*)  d_in[1];
    const float* ew    = (const float*)d_in[2];
    const float* g1_Wl = (const float*)d_in[3];
    const float* g1_Wr = (const float*)d_in[4];
    const float* g1_We = (const float*)d_in[5];
    const float* g1_at = (const float*)d_in[6];
    const float* g2_Wl = (const float*)d_in[8];
    const float* g2_Wr = (const float*)d_in[9];
    const float* g2_We = (const float*)d_in[10];
    const float* g2_at = (const float*)d_in[11];
    const float* n1_g  = (const float*)d_in[13];
    const float* n1_b  = (const float*)d_in[14];
    const float* n2_g  = (const float*)d_in[15];
    const float* n2_b  = (const float*)d_in[16];
    const float* n3_g  = (const float*)d_in[17];
    const float* n3_b  = (const float*)d_in[18];
    const float* ff_W1 = (const float*)d_in[19];
    const float* ff_b1 = (const float*)d_in[20];
    const float* ff_W2 = (const float*)d_in[21];
    const int* src = ei;
    const int* dst = ei + Ee;
    float* out = (float*)d_out;

    void* p;
    cudaGetSymbolAddress(&p, g_xlr);  float* xlr  = (float*)p;
    cudaGetSymbolAddress(&p, g_agg);  float* agg  = (float*)p;
    cudaGetSymbolAddress(&p, g_h1);   float* h1   = (float*)p;
    cudaGetSymbolAddress(&p, g_h2);   float* h2   = (float*)p;
    cudaGetSymbolAddress(&p, g_ff2);  float* ff2  = (float*)p;
    cudaGetSymbolAddress(&p, g_Apk);  __nv_bfloat16* Apk = (__nv_bfloat16*)p;
    cudaGetSymbolAddress(&p, g_Fpk);  __nv_bfloat16* Fpk = (__nv_bfloat16*)p;
    cudaGetSymbolAddress(&p, g_EApk); __nv_bfloat16* EApk = (__nv_bfloat16*)p;
    cudaGetSymbolAddress(&p, g_Wpk);  __nv_bfloat16* Wpk = (__nv_bfloat16*)p;

    cudaFuncSetAttribute(gemm_pk<0>, cudaFuncAttributeMaxDynamicSharedMemorySize, GEMM_SMEM_PK);
    cudaFuncSetAttribute(gemm_pk<1>, cudaFuncAttributeMaxDynamicSharedMemorySize, GEMM_SMEM_PK);
    cudaFuncSetAttribute(gemm_pk<2>, cudaFuncAttributeMaxDynamicSharedMemorySize, GEMM_SMEM_PK);
    cudaFuncSetAttribute(gemm_pk<3>, cudaFuncAttributeMaxDynamicSharedMemorySize, GEMM_SMEM_PK);
    cudaFuncSetAttribute(gemm_score, cudaFuncAttributeMaxDynamicSharedMemorySize, SC_SMEM);

    cudaStream_t sd = 0;
    cudaEvent_t ev0 = nullptr, ev1 = nullptr;
    cudaStreamCreateWithFlags(&sd, cudaStreamNonBlocking);
    cudaEventCreateWithFlags(&ev0, cudaEventDisableTiming);
    cudaEventCreateWithFlags(&ev1, cudaEventDisableTiming);

    // ---- fork: CSR + edge-attr chain on side stream ----
    cudaEventRecord(ev0, 0);
    cudaStreamWaitEvent(sd, ev0, 0);
    k_zero_icnt<<<cdiv(Nn, 256), 256, 0, sd>>>();
    k_count<<<cdiv(Ee, 256), 256, 0, sd>>>(dst);
    k_scan<<<1, 1024, 0, sd>>>();
    k_scatter<<<cdiv(Ee, 256), 256, 0, sd>>>(src, dst);
    k_loop_mean<<<cdiv(Nn, 8), 256, 0, sd>>>(ew);
    k_pack_ea<<<cdiv(ETOT * EDIMc, 256), 256, 0, sd>>>(ew);
    cudaEventRecord(ev1, sd);

    // ---- main stream: weight packs, node pack, xlr GEMM ----
    k_packT_all<<<cdiv(802816, 256), 256>>>(g1_Wl, g1_Wr, g1_We, g2_Wl, g2_Wr, g2_We,
                                            ff_W1, ff_W2, Wpk);
    k_pack_node<<<cdiv(Nn * DIMc, 256), 256>>>(nf, Apk, Nn, DIMc);

    dim3 gXLR(4, cdiv(Nn, 128));
    int nbScore = cdiv(ETOT, 128);
    int nbNode  = cdiv(Nn, 8);

    gemm_pk<2><<<gXLR, 256, GEMM_SMEM_PK>>>(Apk, Wpk + OWLR1, nullptr, xlr, Nn, 768, 512);

    // ---- join ----
    cudaStreamWaitEvent(0, ev1, 0);

    // ---- block 1 ----
    gemm_score<<<nbScore, 512, SC_SMEM>>>(EApk, Wpk + OWE1, g1_at, src, dst);
    k_node<<<nbNode, 256>>>();
    k_bnapply<true><<<cdiv(Nn * DIMc, 256), 256>>>(agg, n1_g, n1_b, nf, h1);

    // ---- block 2 ----
    gemm_pk<2><<<gXLR, 256, GEMM_SMEM_PK>>>(Apk, Wpk + OWLR2, nullptr, xlr, Nn, 768, 512);
    gemm_score<<<nbScore, 512, SC_SMEM>>>(EApk, Wpk + OWE2, g2_at, src, dst);
    k_node<<<nbNode, 256>>>();
    k_bnapply<true><<<cdiv(Nn * DIMc, 256), 256>>>(agg, n2_g, n2_b, h1, h2);

    // ---- feed-forward ----
    dim3 gF1(8, cdiv(Nn, 128));
    gemm_pk<1><<<gF1, 256, GEMM_SMEM_PK>>>(Apk, Wpk + OW1, ff_b1, nullptr, Nn, 768, DFFc);
    dim3 gF2(2, cdiv(Nn, 128));
    gemm_pk<3><<<gF2, 256, GEMM_SMEM_PK>>>(Fpk, Wpk + OW2, nullptr, ff2, Nn, 3072, DIMc);
    k_bnapply<false><<<cdiv(Nn * DIMc, 256), 256>>>(ff2, n3_g, n3_b, h2, out);
}

// round 15
// speedup vs baseline: 1.0822x; 1.0532x over previous
#include <cuda_runtime.h>
#include <cuda_bf16.h>
#include <cuda_fp16.h>
#include <math.h>
#include <stdint.h>

#define Nn    20000
#define Ee    320000
#define DIMc  256
#define Hh    8
#define EDIMc 32
#define DFFc  1024
#define ETOT  (Ee + Nn)

// ---------------- scratch (device globals) -----------------------------------
static __device__ float    g_xlr[(size_t)Nn * 512];
static __device__ __half   g_xlrh[(size_t)Nn * 512];
static __device__ float    g_loop[(size_t)Nn * EDIMc];
static __device__ int      g_icnt[Nn];
static __device__ float    g_sc [(size_t)ETOT * Hh];     // indexed by CSR position
static __device__ float    g_agg[(size_t)Nn * DIMc];
static __device__ float    g_h1 [(size_t)Nn * DIMc];
static __device__ float    g_h2 [(size_t)Nn * DIMc];
static __device__ float    g_ff2[(size_t)Nn * DIMc];
static __device__ float    g_sum[DIMc];
static __device__ float    g_sumsq[DIMc];
static __device__ int      g_rowptr[Nn + 1];
static __device__ int      g_tmp[Nn];
static __device__ int2     g_adj[Ee];                    // {src, edge_id} per CSR pos
static __device__ int      g_pdst[Ee];                   // dst per CSR pos

static __device__ __nv_bfloat16 g_Apk[(size_t)Nn * 768];
static __device__ __nv_bfloat16 g_Fpk[(size_t)Nn * 3072];
static __device__ __nv_bfloat16 g_EApk[(size_t)ETOT * 64];   // CSR-ordered [Ah|Al]
#define OWLR1 0
#define OWE1  393216
#define OWLR2 409600
#define OWE2  802816
#define OW1   819200
#define OW2   1605632
#define WPK_TOTAL 2392064
static __device__ __nv_bfloat16 g_Wpk[WPK_TOTAL];

// ---------------- PTX helpers --------------------------------------------------
__device__ __forceinline__ uint32_t smem_u32(const void* p) {
    uint32_t a;
    asm("{ .reg .u64 t; cvta.to.shared.u64 t, %1; cvt.u32.u64 %0, t; }"
        : "=r"(a) : "l"(p));
    return a;
}
#define LDSM_X4(r0, r1, r2, r3, addr) \
    asm volatile("ldmatrix.sync.aligned.m8n8.x4.shared.b16 {%0,%1,%2,%3}, [%4];" \
                 : "=r"(r0), "=r"(r1), "=r"(r2), "=r"(r3) : "r"(addr))
#define LDSM_X2(r0, r1, addr) \
    asm volatile("ldmatrix.sync.aligned.m8n8.x2.shared.b16 {%0,%1}, [%2];" \
                 : "=r"(r0), "=r"(r1) : "r"(addr))
#define MMA16816(c, a0, a1, a2, a3, b0, b1) \
    asm volatile("mma.sync.aligned.m16n8k16.row.col.f32.bf16.bf16.f32 " \
                 "{%0,%1,%2,%3}, {%4,%5,%6,%7}, {%8,%9}, {%0,%1,%2,%3};" \
                 : "+f"((c)[0]), "+f"((c)[1]), "+f"((c)[2]), "+f"((c)[3]) \
                 : "r"(a0), "r"(a1), "r"(a2), "r"(a3), "r"(b0), "r"(b1))
__device__ __forceinline__ void cp_cg(uint32_t dst, const void* src, int sz) {
    asm volatile("cp.async.cg.shared.global [%0], [%1], 16, %2;"
                 :: "r"(dst), "l"(src), "r"(sz));
}
#define CP_COMMIT() asm volatile("cp.async.commit_group;" ::: "memory")
#define SMEM_SWZ(b) ((b) ^ (((b) >> 3) & 0x70))

// ---------------- pack kernels --------------------------------------------------
__global__ void k_pack_node(const float* __restrict__ X, __nv_bfloat16* __restrict__ A,
                            int rows, int K) {
    int i = blockIdx.x * blockDim.x + threadIdx.x;
    if (i >= rows * K) return;
    int r = i / K, k = i - r * K;
    float v = X[i];
    __nv_bfloat16 h = __float2bfloat16(v);
    __nv_bfloat16 l = __float2bfloat16(v - __bfloat162float(h));
    size_t b = (size_t)r * (3 * K);
    A[b + k] = h;
    A[b + K + k] = l;
    A[b + 2 * K + k] = h;
}
// edge attrs packed in CSR-position order (gather by edge id; runs once, side stream)
__global__ void k_pack_ea(const float* __restrict__ ew) {
    int i = blockIdx.x * blockDim.x + threadIdx.x;
    if (i >= ETOT * EDIMc) return;
    int r = i >> 5, k = i & 31;
    float v;
    if (r < Ee) {
        int eid = g_adj[r].y;
        v = ew[(size_t)eid * EDIMc + k];
    } else {
        v = g_loop[(size_t)(r - Ee) * EDIMc + k];
    }
    __nv_bfloat16 h = __float2bfloat16(v);
    __nv_bfloat16 l = __float2bfloat16(v - __bfloat162float(h));
    size_t b = (size_t)r * 64;
    g_EApk[b + k]      = h;
    g_EApk[b + 32 + k] = l;
}
__device__ __forceinline__ void pack_w_one(const float* __restrict__ W,
                                           __nv_bfloat16* __restrict__ WT,
                                           int i, int K, int N, int Kp) {
    int k = i / N, n = i - k * N;
    float v = W[i];
    __nv_bfloat16 h = __float2bfloat16(v);
    __nv_bfloat16 l = __float2bfloat16(v - __bfloat162float(h));
    size_t b = (size_t)n * Kp;
    WT[b + k]         = h;
    WT[b + K + k]     = h;
    WT[b + 2 * K + k] = l;
    if (k < Kp - 3 * K) WT[b + 3 * K + k] = __float2bfloat16(0.f);
}
__device__ __forceinline__ void pack_w_x2(const float* __restrict__ W,
                                          __nv_bfloat16* __restrict__ WT, int i) {
    int k = i >> 8, n = i & 255;
    __nv_bfloat16 h = __float2bfloat16(W[i]);
    WT[n * 64 + k]      = h;
    WT[n * 64 + 32 + k] = h;
}
__global__ void k_packT_all(const float* w0, const float* w1, const float* w2,
                            const float* w3, const float* w4, const float* w5,
                            const float* w6, const float* w7,
                            __nv_bfloat16* __restrict__ WT) {
    int i = blockIdx.x * blockDim.x + threadIdx.x;
    if (i < 65536)        pack_w_one(w0, WT + OWLR1,          i,           DIMc, DIMc, 768);
    else if (i < 131072)  pack_w_one(w1, WT + OWLR1 + 196608, i - 65536,   DIMc, DIMc, 768);
    else if (i < 139264)  pack_w_x2 (w2, WT + OWE1,           i - 131072);
    else if (i < 204800)  pack_w_one(w3, WT + OWLR2,          i - 139264,  DIMc, DIMc, 768);
    else if (i < 270336)  pack_w_one(w4, WT + OWLR2 + 196608, i - 204800,  DIMc, DIMc, 768);
    else if (i < 278528)  pack_w_x2 (w5, WT + OWE2,           i - 270336);
    else if (i < 540672)  pack_w_one(w6, WT + OW1,            i - 278528,  DIMc, DFFc, 768);
    else if (i < 802816)  pack_w_one(w7, WT + OW2,            i - 540672,  DFFc, DIMc, 3072);
}

// ---------------- 3-stage pipelined bf16 GEMM (K-packed x3) --------------------
#define GEMM_SMEM_PK 98304

template<int EPI>
__global__ void __launch_bounds__(256, 2) gemm_pk(
    const __nv_bfloat16* __restrict__ A, const __nv_bfloat16* __restrict__ BT,
    const float* __restrict__ bias, float* __restrict__ C,
    int M, int Kp, int Nc) {
    extern __shared__ __nv_bfloat16 sm[];
    __shared__ float s_st[512];
    uint32_t sb = smem_u32(sm);
    int tid  = threadIdx.x;
    int lane = tid & 31;
    int w    = tid >> 5;
    int wr   = w & 1;
    int wc   = w >> 1;
    int row0 = blockIdx.y * 128;
    int col0 = blockIdx.x * 128;

    if (EPI == 1 && blockIdx.x == 0 && blockIdx.y == 0 && tid < 256) {
        g_sum[tid] = 0.f; g_sumsq[tid] = 0.f;
    }
    if (EPI == 3) { s_st[tid] = 0.f; s_st[tid + 256] = 0.f; }

    float acc[4][4][4];
#pragma unroll
    for (int i = 0; i < 4; i++)
#pragma unroll
        for (int j = 0; j < 4; j++)
#pragma unroll
            for (int q = 0; q < 4; q++) acc[i][j][q] = 0.f;

    const int nch = Kp >> 6;

    auto issue = [&](int c) {
        if (c < nch) {
            int stage = c % 3;
            uint32_t sA = sb + (uint32_t)stage * 32768u;
            uint32_t sB = sA + 16384u;
            int k0 = c << 6;
#pragma unroll
            for (int p = 0; p < 4; p++) {
                int idx = tid + (p << 8);
                int row = idx >> 3, u = idx & 7;
                uint32_t soff = SMEM_SWZ((uint32_t)(row * 128 + u * 16));
                int gr = row0 + row;
                cp_cg(sA + soff, A + (size_t)gr * Kp + k0 + u * 8, gr < M ? 16 : 0);
                cp_cg(sB + soff, BT + (size_t)(col0 + row) * Kp + k0 + u * 8, 16);
            }
        }
        CP_COMMIT();
    };
    auto compute = [&](int c) {
        int stage = c % 3;
        uint32_t bA = sb + (uint32_t)stage * 32768u;
        uint32_t bB = bA + 16384u;
#pragma unroll
        for (int ks = 0; ks < 4; ks++) {
            uint32_t a[4][4], b[4][2];
#pragma unroll
            for (int mi = 0; mi < 4; mi++) {
                uint32_t byte = (uint32_t)((wr * 64 + mi * 16 + (lane & 15)) * 128 +
                                           ks * 32 + ((lane >> 4) << 4));
                LDSM_X4(a[mi][0], a[mi][1], a[mi][2], a[mi][3], bA + SMEM_SWZ(byte));
            }
#pragma unroll
            for (int ni = 0; ni < 4; ni++) {
                uint32_t byte = (uint32_t)((wc * 32 + ni * 8 + (lane & 7)) * 128 +
                                           ks * 32 + (((lane >> 3) & 1) << 4));
                LDSM_X2(b[ni][0], b[ni][1], bB + SMEM_SWZ(byte));
            }
#pragma unroll
            for (int mi = 0; mi < 4; mi++)
#pragma unroll
                for (int ni = 0; ni < 4; ni++)
                    MMA16816(acc[mi][ni], a[mi][0], a[mi][1], a[mi][2], a[mi][3],
                             b[ni][0], b[ni][1]);
        }
    };

    issue(0);
    issue(1);
    for (int c = 0; c < nch; c++) {
        asm volatile("cp.async.wait_group 1;" ::: "memory");
        __syncthreads();
        issue(c + 2);
        compute(c);
    }

    float cs[4][2], cq[4][2];
    if (EPI == 3) {
#pragma unroll
        for (int ni = 0; ni < 4; ni++) {
            cs[ni][0] = cs[ni][1] = 0.f;
            cq[ni][0] = cq[ni][1] = 0.f;
        }
    }

#pragma unroll
    for (int mi = 0; mi < 4; mi++) {
#pragma unroll
        for (int ni = 0; ni < 4; ni++) {
            int r = row0 + wr * 64 + mi * 16 + (lane >> 2);
            int c = col0 + wc * 32 + ni * 8 + (lane & 3) * 2;
            float v0 = acc[mi][ni][0], v1 = acc[mi][ni][1];
            float v2 = acc[mi][ni][2], v3 = acc[mi][ni][3];
            if (EPI == 1) {
                float b0 = bias[c], b1 = bias[c + 1];
                v0 = fmaxf(v0 + b0, 0.f); v1 = fmaxf(v1 + b1, 0.f);
                v2 = fmaxf(v2 + b0, 0.f); v3 = fmaxf(v3 + b1, 0.f);
                __nv_bfloat16* P = g_Fpk;
#pragma unroll
                for (int hh = 0; hh < 2; hh++) {
                    int rr = r + hh * 8;
                    if (rr >= M) continue;
                    float u0 = hh ? v2 : v0, u1 = hh ? v3 : v1;
                    size_t base = (size_t)rr * 3072 + c;
                    __nv_bfloat162 hp = __floats2bfloat162_rn(u0, u1);
                    __nv_bfloat162 lp = __floats2bfloat162_rn(
                        u0 - __bfloat162float(hp.x), u1 - __bfloat162float(hp.y));
                    *(__nv_bfloat162*)&P[base]        = hp;
                    *(__nv_bfloat162*)&P[base + 1024] = lp;
                    *(__nv_bfloat162*)&P[base + 2048] = hp;
                }
            } else {
                if (r < M) {
                    C[(size_t)r * Nc + c] = v0;
                    C[(size_t)r * Nc + c + 1] = v1;
                    if (EPI == 2)
                        *(__half2*)(g_xlrh + (size_t)r * 512 + c) = __floats2half2_rn(v0, v1);
                    if (EPI == 3) {
                        cs[ni][0] += v0; cq[ni][0] += v0 * v0;
                        cs[ni][1] += v1; cq[ni][1] += v1 * v1;
                    }
                }
                if (r + 8 < M) {
                    C[(size_t)(r + 8) * Nc + c] = v2;
                    C[(size_t)(r + 8) * Nc + c + 1] = v3;
                    if (EPI == 2)
                        *(__half2*)(g_xlrh + (size_t)(r + 8) * 512 + c) = __floats2half2_rn(v2, v3);
                    if (EPI == 3) {
                        cs[ni][0] += v2; cq[ni][0] += v2 * v2;
                        cs[ni][1] += v3; cq[ni][1] += v3 * v3;
                    }
                }
            }
        }
    }
    if (EPI == 3) {
        __syncthreads();
#pragma unroll
        for (int ni = 0; ni < 4; ni++) {
            int gc = col0 + wc * 32 + ni * 8 + (lane & 3) * 2;
            atomicAdd(&s_st[gc],       cs[ni][0]);
            atomicAdd(&s_st[gc + 1],   cs[ni][1]);
            atomicAdd(&s_st[256 + gc],     cq[ni][0]);
            atomicAdd(&s_st[256 + gc + 1], cq[ni][1]);
        }
        __syncthreads();
        if (tid < 256) {
            atomicAdd(&g_sum[tid],   s_st[tid]);
            atomicAdd(&g_sumsq[tid], s_st[tid + 256]);
        }
    }
}

// ---------------- ee GEMM (Kp=64, x2 pack, CSR-ordered) + GATv2 score -----------
#define SC_SMEM 55296

__global__ void __launch_bounds__(512, 1) gemm_score(
    const __nv_bfloat16* __restrict__ A, const __nv_bfloat16* __restrict__ BT,
    const float* __restrict__ att) {
    extern __shared__ char smc[];
    uint32_t sb = smem_u32(smc);
    float* sc_s  = (float*)(smc + 49152);
    float* att_s = (float*)(smc + 53248);
    int*   ss_s  = (int*)(smc + 54272);
    int*   sd_s  = (int*)(smc + 54784);
    int tid = threadIdx.x, lane = tid & 31, w = tid >> 5;
    int wr = w & 3, wc = w >> 2;
    int row0 = blockIdx.x * 128;

    if (blockIdx.x == 0 && tid < 256) { g_sum[tid] = 0.f; g_sumsq[tid] = 0.f; }

    if (tid < 256) att_s[tid] = att[tid];
    if (tid < 128) {
        int e = row0 + tid;                    // CSR position
        int s, d;
        if (e < Ee)       { s = g_adj[e].x; d = g_pdst[e]; }
        else if (e < ETOT){ s = e - Ee; d = s; }
        else              { s = 0; d = 0; }
        ss_s[tid] = s; sd_s[tid] = d;
    }
#pragma unroll
    for (int p = 0; p < 2; p++) {
        int j = tid + (p << 9);
        int row = j >> 3, u = j & 7;
        uint32_t soff = SMEM_SWZ((uint32_t)(row * 128 + u * 16));
        int gr = row0 + row;
        cp_cg(sb + soff, A + (size_t)gr * 64 + u * 8, gr < ETOT ? 16 : 0);
    }
#pragma unroll
    for (int p = 0; p < 4; p++) {
        int j = tid + (p << 9);
        int row = j >> 3, u = j & 7;
        uint32_t soff = 16384u + SMEM_SWZ((uint32_t)(row * 128 + u * 16));
        cp_cg(sb + soff, BT + (size_t)row * 64 + u * 8, 16);
    }
    CP_COMMIT();
    asm volatile("cp.async.wait_group 0;" ::: "memory");
    __syncthreads();

    float acc[2][8][4];
#pragma unroll
    for (int i = 0; i < 2; i++)
#pragma unroll
        for (int j = 0; j < 8; j++)
#pragma unroll
            for (int q = 0; q < 4; q++) acc[i][j][q] = 0.f;

    uint32_t bA = sb;
    uint32_t bB = sb + 16384u;
#pragma unroll
    for (int ks = 0; ks < 4; ks++) {
        uint32_t a[2][4], b[8][2];
#pragma unroll
        for (int mi = 0; mi < 2; mi++) {
            uint32_t byte = (uint32_t)((wr * 32 + mi * 16 + (lane & 15)) * 128 +
                                       ks * 32 + ((lane >> 4) << 4));
            LDSM_X4(a[mi][0], a[mi][1], a[mi][2], a[mi][3], bA + SMEM_SWZ(byte));
        }
#pragma unroll
        for (int ni = 0; ni < 8; ni++) {
            uint32_t byte = (uint32_t)((wc * 64 + ni * 8 + (lane & 7)) * 128 +
                                       ks * 32 + (((lane >> 3) & 1) << 4));
            LDSM_X2(b[ni][0], b[ni][1], bB + SMEM_SWZ(byte));
        }
#pragma unroll
        for (int mi = 0; mi < 2; mi++)
#pragma unroll
            for (int ni = 0; ni < 8; ni++)
                MMA16816(acc[mi][ni], a[mi][0], a[mi][1], a[mi][2], a[mi][3],
                         b[ni][0], b[ni][1]);
    }

#pragma unroll
    for (int mi = 0; mi < 2; mi++) {
#pragma unroll
        for (int hf = 0; hf < 2; hf++) {
            int r = wr * 32 + mi * 16 + (lane >> 2) + hf * 8;
            int s = ss_s[r], d = sd_s[r];
            const __half* xlp = g_xlrh + (size_t)s * 512;
            const __half* xrp = g_xlrh + (size_t)d * 512 + 256;
            float h0 = 0.f, h1 = 0.f;
#pragma unroll
            for (int ni = 0; ni < 8; ni++) {
                int c0 = wc * 64 + ni * 8 + (lane & 3) * 2;
                float2 xlv = __half22float2(*(const __half2*)(xlp + c0));
                float2 xrv = __half22float2(*(const __half2*)(xrp + c0));
                float z0 = acc[mi][ni][hf * 2 + 0] + xlv.x + xrv.x;
                float z1 = acc[mi][ni][hf * 2 + 1] + xlv.y + xrv.y;
                z0 = (z0 > 0.f) ? z0 : 0.2f * z0;
                z1 = (z1 > 0.f) ? z1 : 0.2f * z1;
                float pp = z0 * att_s[c0] + z1 * att_s[c0 + 1];
                if (ni < 4) h0 += pp; else h1 += pp;
            }
            h0 += __shfl_xor_sync(0xffffffffu, h0, 1);
            h0 += __shfl_xor_sync(0xffffffffu, h0, 2);
            h1 += __shfl_xor_sync(0xffffffffu, h1, 1);
            h1 += __shfl_xor_sync(0xffffffffu, h1, 2);
            if ((lane & 3) == 0) {
                sc_s[r * 8 + wc * 2]     = h0;
                sc_s[r * 8 + wc * 2 + 1] = h1;
            }
        }
    }
    __syncthreads();
#pragma unroll
    for (int p = 0; p < 2; p++) {
        int i = tid + (p << 9);
        int r = i >> 3;
        int e = row0 + r;
        if (e < ETOT) g_sc[(size_t)e * 8 + (i & 7)] = sc_s[i];
    }
}

// ---------------- CSR build ------------------------------------------------------
__global__ void k_zero_icnt() {
    int i = blockIdx.x * blockDim.x + threadIdx.x;
    if (i < Nn) g_icnt[i] = 0;
}
__global__ void k_count(const int* __restrict__ dst) {
    int e = blockIdx.x * blockDim.x + threadIdx.x;
    if (e < Ee) atomicAdd(&g_icnt[dst[e]], 1);
}
__global__ void k_scan() {
    __shared__ int part[1024];
    int t = threadIdx.x;
    const int SEG = (Nn + 1023) / 1024;
    int base = t * SEG;
    int s = 0;
    for (int i = 0; i < SEG; i++) {
        int idx = base + i;
        if (idx < Nn) s += g_icnt[idx];
    }
    part[t] = s;
    __syncthreads();
    for (int off = 1; off < 1024; off <<= 1) {
        int v = (t >= off) ? part[t - off] : 0;
        __syncthreads();
        part[t] += v;
        __syncthreads();
    }
    int run = (t == 0) ? 0 : part[t - 1];
    for (int i = 0; i < SEG; i++) {
        int idx = base + i;
        if (idx < Nn) {
            g_rowptr[idx] = run;
            g_tmp[idx] = run;
            run += g_icnt[idx];
        }
    }
    if (t == 1023) g_rowptr[Nn] = run;
}
__global__ void k_scatter(const int* __restrict__ src, const int* __restrict__ dst) {
    int e = blockIdx.x * blockDim.x + threadIdx.x;
    if (e >= Ee) return;
    int d = dst[e];
    int pos = atomicAdd(&g_tmp[d], 1);
    g_adj[pos] = make_int2(src[e], e);
    g_pdst[pos] = d;
}
__global__ void k_loop_mean(const float* __restrict__ ew) {
    int d    = blockIdx.x * 8 + (threadIdx.x >> 5);
    int lane = threadIdx.x & 31;
    if (d >= Nn) return;
    int beg = g_rowptr[d], end = g_rowptr[d + 1];
    float s = 0.f;
    for (int i = beg; i < end; i++)
        s += ew[(size_t)g_adj[i].y * EDIMc + lane];
    g_loop[(size_t)d * EDIMc + lane] = s / fmaxf((float)(end - beg), 1.f);
}

// ---------------- per-node softmax + aggregation (fp16 gather, CSR scores) ------
__device__ __forceinline__ void acc_h8(float* acc, const __half* xp, float w) {
    uint4 raw = *(const uint4*)xp;
    const __half2* hp = (const __half2*)&raw;
    float2 f0 = __half22float2(hp[0]);
    float2 f1 = __half22float2(hp[1]);
    float2 f2 = __half22float2(hp[2]);
    float2 f3 = __half22float2(hp[3]);
    acc[0] += w * f0.x; acc[1] += w * f0.y;
    acc[2] += w * f1.x; acc[3] += w * f1.y;
    acc[4] += w * f2.x; acc[5] += w * f2.y;
    acc[6] += w * f3.x; acc[7] += w * f3.y;
}
__global__ void k_node() {
    __shared__ float s_st[512];
    int tid  = threadIdx.x;
    int d    = blockIdx.x * 8 + (tid >> 5);
    int lane = tid & 31;
    s_st[tid] = 0.f;
    s_st[tid + 256] = 0.f;
    __syncthreads();

    int beg = g_rowptr[d], end = g_rowptr[d + 1];
    const float* ssc = g_sc + (size_t)(Ee + d) * Hh;

    int hh = lane >> 2;
    int c0 = lane << 3;

    float den;
    float acc[8];
#pragma unroll
    for (int q = 0; q < 8; q++) acc[q] = 0.f;
    {
        float a = __expf(ssc[hh]);
        den = a;
        acc_h8(acc, g_xlrh + (size_t)d * 512 + c0, a);
    }
    int i = beg;
    for (; i + 1 < end; i += 2) {
        int s0i = g_adj[i].x, s1i = g_adj[i + 1].x;
        float s0 = g_sc[(size_t)i * Hh + hh];           // CSR-contiguous
        float s1 = g_sc[(size_t)(i + 1) * Hh + hh];
        float w0 = __expf(s0), w1 = __expf(s1);
        den += w0 + w1;
        acc_h8(acc, g_xlrh + (size_t)s0i * 512 + c0, w0);
        acc_h8(acc, g_xlrh + (size_t)s1i * 512 + c0, w1);
    }
    if (i < end) {
        int s0i = g_adj[i].x;
        float w0 = __expf(g_sc[(size_t)i * Hh + hh]);
        den += w0;
        acc_h8(acc, g_xlrh + (size_t)s0i * 512 + c0, w0);
    }
    float inv = 1.f / den;
#pragma unroll
    for (int q = 0; q < 8; q++) acc[q] *= inv;

    float4* op = (float4*)(g_agg + (size_t)d * DIMc + c0);
    op[0] = make_float4(acc[0], acc[1], acc[2], acc[3]);
    op[1] = make_float4(acc[4], acc[5], acc[6], acc[7]);

#pragma unroll
    for (int q = 0; q < 8; q++) {
        atomicAdd(&s_st[c0 + q], acc[q]);
        atomicAdd(&s_st[256 + c0 + q], acc[q] * acc[q]);
    }
    __syncthreads();
    if (tid < 256) {
        atomicAdd(&g_sum[tid], s_st[tid]);
        atomicAdd(&g_sumsq[tid], s_st[tid + 256]);
    }
}

// ---------------- BatchNorm apply -------------------------------------------------
template<bool PACK>
__global__ void k_bnapply(const float* __restrict__ X, const float* __restrict__ gam,
                          const float* __restrict__ bet, const float* __restrict__ res,
                          float* __restrict__ out) {
    int i = blockIdx.x * blockDim.x + threadIdx.x;
    if (i >= Nn * DIMc) return;
    int c = i & (DIMc - 1);
    float mu  = g_sum[c]   * (1.f / Nn);
    float var = g_sumsq[c] * (1.f / Nn) - mu * mu;
    float y = (X[i] - mu) * rsqrtf(var + 1e-5f) * gam[c] + bet[c];
    y = (y > 0.f) ? y : 0.01f * y;
    float v = res[i] + y;
    out[i] = v;
    if (PACK) {
        int r = i >> 8;
        __nv_bfloat16 h = __float2bfloat16(v);
        size_t b = (size_t)r * 768 + c;
        g_Apk[b]       = h;
        g_Apk[b + 256] = __float2bfloat16(v - __bfloat162float(h));
        g_Apk[b + 512] = h;
    }
}

// ---------------- host orchestration ----------------------------------------------
static inline int cdiv(int a, int b) { return (a + b - 1) / b; }

extern "C" void kernel_launch(void* const* d_in, const int* in_sizes, int n_in,
                              void* d_out, int out_size) {
    const float* nf    = (const float*)d_in[0];
    const int*   ei    = (const int*)  d_in[1];
    const float* ew    = (const float*)d_in[2];
    const float* g1_Wl = (const float*)d_in[3];
    const float* g1_Wr = (const float*)d_in[4];
    const float* g1_We = (const float*)d_in[5];
    const float* g1_at = (const float*)d_in[6];
    const float* g2_Wl = (const float*)d_in[8];
    const float* g2_Wr = (const float*)d_in[9];
    const float* g2_We = (const float*)d_in[10];
    const float* g2_at = (const float*)d_in[11];
    const float* n1_g  = (const float*)d_in[13];
    const float* n1_b  = (const float*)d_in[14];
    const float* n2_g  = (const float*)d_in[15];
    const float* n2_b  = (const float*)d_in[16];
    const float* n3_g  = (const float*)d_in[17];
    const float* n3_b  = (const float*)d_in[18];
    const float* ff_W1 = (const float*)d_in[19];
    const float* ff_b1 = (const float*)d_in[20];
    const float* ff_W2 = (const float*)d_in[21];
    const int* src = ei;
    const int* dst = ei + Ee;
    float* out = (float*)d_out;

    void* p;
    cudaGetSymbolAddress(&p, g_xlr);  float* xlr  = (float*)p;
    cudaGetSymbolAddress(&p, g_agg);  float* agg  = (float*)p;
    cudaGetSymbolAddress(&p, g_h1);   float* h1   = (float*)p;
    cudaGetSymbolAddress(&p, g_h2);   float* h2   = (float*)p;
    cudaGetSymbolAddress(&p, g_ff2);  float* ff2  = (float*)p;
    cudaGetSymbolAddress(&p, g_Apk);  __nv_bfloat16* Apk = (__nv_bfloat16*)p;
    cudaGetSymbolAddress(&p, g_Fpk);  __nv_bfloat16* Fpk = (__nv_bfloat16*)p;
    cudaGetSymbolAddress(&p, g_EApk); __nv_bfloat16* EApk = (__nv_bfloat16*)p;
    cudaGetSymbolAddress(&p, g_Wpk);  __nv_bfloat16* Wpk = (__nv_bfloat16*)p;

    cudaFuncSetAttribute(gemm_pk<0>, cudaFuncAttributeMaxDynamicSharedMemorySize, GEMM_SMEM_PK);
    cudaFuncSetAttribute(gemm_pk<1>, cudaFuncAttributeMaxDynamicSharedMemorySize, GEMM_SMEM_PK);
    cudaFuncSetAttribute(gemm_pk<2>, cudaFuncAttributeMaxDynamicSharedMemorySize, GEMM_SMEM_PK);
    cudaFuncSetAttribute(gemm_pk<3>, cudaFuncAttributeMaxDynamicSharedMemorySize, GEMM_SMEM_PK);
    cudaFuncSetAttribute(gemm_score, cudaFuncAttributeMaxDynamicSharedMemorySize, SC_SMEM);

    cudaStream_t sd = 0;
    cudaEvent_t ev0 = nullptr, ev1 = nullptr;
    cudaStreamCreateWithFlags(&sd, cudaStreamNonBlocking);
    cudaEventCreateWithFlags(&ev0, cudaEventDisableTiming);
    cudaEventCreateWithFlags(&ev1, cudaEventDisableTiming);

    // ---- fork: CSR + edge-attr chain on side stream ----
    cudaEventRecord(ev0, 0);
    cudaStreamWaitEvent(sd, ev0, 0);
    k_zero_icnt<<<cdiv(Nn, 256), 256, 0, sd>>>();
    k_count<<<cdiv(Ee, 256), 256, 0, sd>>>(dst);
    k_scan<<<1, 1024, 0, sd>>>();
    k_scatter<<<cdiv(Ee, 256), 256, 0, sd>>>(src, dst);
    k_loop_mean<<<cdiv(Nn, 8), 256, 0, sd>>>(ew);
    k_pack_ea<<<cdiv(ETOT * EDIMc, 256), 256, 0, sd>>>(ew);
    cudaEventRecord(ev1, sd);

    // ---- main stream: weight packs, node pack, xlr GEMM ----
    k_packT_all<<<cdiv(802816, 256), 256>>>(g1_Wl, g1_Wr, g1_We, g2_Wl, g2_Wr, g2_We,
                                            ff_W1, ff_W2, Wpk);
    k_pack_node<<<cdiv(Nn * DIMc, 256), 256>>>(nf, Apk, Nn, DIMc);

    dim3 gXLR(4, cdiv(Nn, 128));
    int nbScore = cdiv(ETOT, 128);
    int nbNode  = cdiv(Nn, 8);

    gemm_pk<2><<<gXLR, 256, GEMM_SMEM_PK>>>(Apk, Wpk + OWLR1, nullptr, xlr, Nn, 768, 512);

    // ---- join ----
    cudaStreamWaitEvent(0, ev1, 0);

    // ---- block 1 ----
    gemm_score<<<nbScore, 512, SC_SMEM>>>(EApk, Wpk + OWE1, g1_at);
    k_node<<<nbNode, 256>>>();
    k_bnapply<true><<<cdiv(Nn * DIMc, 256), 256>>>(agg, n1_g, n1_b, nf, h1);

    // ---- block 2 ----
    gemm_pk<2><<<gXLR, 256, GEMM_SMEM_PK>>>(Apk, Wpk + OWLR2, nullptr, xlr, Nn, 768, 512);
    gemm_score<<<nbScore, 512, SC_SMEM>>>(EApk, Wpk + OWE2, g2_at);
    k_node<<<nbNode, 256>>>();
    k_bnapply<true><<<cdiv(Nn * DIMc, 256), 256>>>(agg, n2_g, n2_b, h1, h2);

    // ---- feed-forward ----
    dim3 gF1(8, cdiv(Nn, 128));
    gemm_pk<1><<<gF1, 256, GEMM_SMEM_PK>>>(Apk, Wpk + OW1, ff_b1, nullptr, Nn, 768, DFFc);
    dim3 gF2(2, cdiv(Nn, 128));
    gemm_pk<3><<<gF2, 256, GEMM_SMEM_PK>>>(Fpk, Wpk + OW2, nullptr, ff2, Nn, 3072, DIMc);
    k_bnapply<false><<<cdiv(Nn * DIMc, 256), 256>>>(ff2, n3_g, n3_b, h2, out);
}

// round 16
// speedup vs baseline: 1.1102x; 1.0259x over previous
#include <cuda_runtime.h>
#include <cuda_bf16.h>
#include <cuda_fp16.h>
#include <math.h>
#include <stdint.h>

#define Nn    20000
#define Ee    320000
#define DIMc  256
#define Hh    8
#define EDIMc 32
#define DFFc  1024
#define ETOT  (Ee + Nn)

// ---------------- scratch (device globals) -----------------------------------
static __device__ __half   g_xlrh[(size_t)Nn * 512];     // fp16 [xl | xr] (only copy)
static __device__ float    g_loop[(size_t)Nn * EDIMc];
static __device__ int      g_icnt[Nn];
static __device__ float    g_sc [(size_t)ETOT * Hh];     // indexed by CSR position
static __device__ float    g_agg[(size_t)Nn * DIMc];
static __device__ float    g_h1 [(size_t)Nn * DIMc];
static __device__ float    g_h2 [(size_t)Nn * DIMc];
static __device__ float    g_ff2[(size_t)Nn * DIMc];
static __device__ float    g_sum[DIMc];
static __device__ float    g_sumsq[DIMc];
static __device__ int      g_rowptr[Nn + 1];
static __device__ int      g_tmp[Nn];
static __device__ int2     g_adj[Ee];                    // {src, edge_id} per CSR pos
static __device__ int      g_pdst[Ee];                   // dst per CSR pos

static __device__ __nv_bfloat16 g_Apk[(size_t)Nn * 768];
static __device__ __nv_bfloat16 g_Fpk[(size_t)Nn * 3072];
static __device__ __nv_bfloat16 g_EApk[(size_t)ETOT * 64];   // CSR-ordered [Ah|Al]
#define OWLR1 0
#define OWE1  393216
#define OWLR2 409600
#define OWE2  802816
#define OW1   819200
#define OW2   1605632
#define WPK_TOTAL 2392064
static __device__ __nv_bfloat16 g_Wpk[WPK_TOTAL];

// ---------------- PTX helpers --------------------------------------------------
__device__ __forceinline__ uint32_t smem_u32(const void* p) {
    uint32_t a;
    asm("{ .reg .u64 t; cvta.to.shared.u64 t, %1; cvt.u32.u64 %0, t; }"
        : "=r"(a) : "l"(p));
    return a;
}
#define LDSM_X4(r0, r1, r2, r3, addr) \
    asm volatile("ldmatrix.sync.aligned.m8n8.x4.shared.b16 {%0,%1,%2,%3}, [%4];" \
                 : "=r"(r0), "=r"(r1), "=r"(r2), "=r"(r3) : "r"(addr))
#define LDSM_X2(r0, r1, addr) \
    asm volatile("ldmatrix.sync.aligned.m8n8.x2.shared.b16 {%0,%1}, [%2];" \
                 : "=r"(r0), "=r"(r1) : "r"(addr))
#define MMA16816(c, a0, a1, a2, a3, b0, b1) \
    asm volatile("mma.sync.aligned.m16n8k16.row.col.f32.bf16.bf16.f32 " \
                 "{%0,%1,%2,%3}, {%4,%5,%6,%7}, {%8,%9}, {%0,%1,%2,%3};" \
                 : "+f"((c)[0]), "+f"((c)[1]), "+f"((c)[2]), "+f"((c)[3]) \
                 : "r"(a0), "r"(a1), "r"(a2), "r"(a3), "r"(b0), "r"(b1))
__device__ __forceinline__ void cp_cg(uint32_t dst, const void* src, int sz) {
    asm volatile("cp.async.cg.shared.global [%0], [%1], 16, %2;"
                 :: "r"(dst), "l"(src), "r"(sz));
}
#define CP_COMMIT() asm volatile("cp.async.commit_group;" ::: "memory")
#define SMEM_SWZ(b) ((b) ^ (((b) >> 3) & 0x70))

// ---------------- pack kernels --------------------------------------------------
__global__ void k_pack_node(const float* __restrict__ X, __nv_bfloat16* __restrict__ A,
                            int rows, int K) {
    int i = blockIdx.x * blockDim.x + threadIdx.x;
    if (i >= rows * K) return;
    int r = i / K, k = i - r * K;
    float v = X[i];
    __nv_bfloat16 h = __float2bfloat16(v);
    __nv_bfloat16 l = __float2bfloat16(v - __bfloat162float(h));
    size_t b = (size_t)r * (3 * K);
    A[b + k] = h;
    A[b + K + k] = l;
    A[b + 2 * K + k] = h;
}
__global__ void k_pack_ea(const float* __restrict__ ew) {
    int i = blockIdx.x * blockDim.x + threadIdx.x;
    if (i >= ETOT * EDIMc) return;
    int r = i >> 5, k = i & 31;
    float v;
    if (r < Ee) {
        int eid = g_adj[r].y;
        v = ew[(size_t)eid * EDIMc + k];
    } else {
        v = g_loop[(size_t)(r - Ee) * EDIMc + k];
    }
    __nv_bfloat16 h = __float2bfloat16(v);
    __nv_bfloat16 l = __float2bfloat16(v - __bfloat162float(h));
    size_t b = (size_t)r * 64;
    g_EApk[b + k]      = h;
    g_EApk[b + 32 + k] = l;
}
__device__ __forceinline__ void pack_w_one(const float* __restrict__ W,
                                           __nv_bfloat16* __restrict__ WT,
                                           int i, int K, int N, int Kp) {
    int k = i / N, n = i - k * N;
    float v = W[i];
    __nv_bfloat16 h = __float2bfloat16(v);
    __nv_bfloat16 l = __float2bfloat16(v - __bfloat162float(h));
    size_t b = (size_t)n * Kp;
    WT[b + k]         = h;
    WT[b + K + k]     = h;
    WT[b + 2 * K + k] = l;
    if (k < Kp - 3 * K) WT[b + 3 * K + k] = __float2bfloat16(0.f);
}
__device__ __forceinline__ void pack_w_x2(const float* __restrict__ W,
                                          __nv_bfloat16* __restrict__ WT, int i) {
    int k = i >> 8, n = i & 255;
    __nv_bfloat16 h = __float2bfloat16(W[i]);
    WT[n * 64 + k]      = h;
    WT[n * 64 + 32 + k] = h;
}
__global__ void k_packT_all(const float* w0, const float* w1, const float* w2,
                            const float* w3, const float* w4, const float* w5,
                            const float* w6, const float* w7,
                            __nv_bfloat16* __restrict__ WT) {
    int i = blockIdx.x * blockDim.x + threadIdx.x;
    if (i < 65536)        pack_w_one(w0, WT + OWLR1,          i,           DIMc, DIMc, 768);
    else if (i < 131072)  pack_w_one(w1, WT + OWLR1 + 196608, i - 65536,   DIMc, DIMc, 768);
    else if (i < 139264)  pack_w_x2 (w2, WT + OWE1,           i - 131072);
    else if (i < 204800)  pack_w_one(w3, WT + OWLR2,          i - 139264,  DIMc, DIMc, 768);
    else if (i < 270336)  pack_w_one(w4, WT + OWLR2 + 196608, i - 204800,  DIMc, DIMc, 768);
    else if (i < 278528)  pack_w_x2 (w5, WT + OWE2,           i - 270336);
    else if (i < 540672)  pack_w_one(w6, WT + OW1,            i - 278528,  DIMc, DFFc, 768);
    else if (i < 802816)  pack_w_one(w7, WT + OW2,            i - 540672,  DFFc, DIMc, 3072);
}

// ---------------- 3-stage pipelined bf16 GEMM (K-packed x3) --------------------
// EPI: 0 = fp32 out; 1 = relu+bias -> pack in g_Fpk (+zero BN stats in blk0);
//      2 = fp16 shadow ONLY (xl/xr; fp32 copy is dead); 3 = fp32 + fused BN stats
#define GEMM_SMEM_PK 98304

template<int EPI>
__global__ void __launch_bounds__(256, 2) gemm_pk(
    const __nv_bfloat16* __restrict__ A, const __nv_bfloat16* __restrict__ BT,
    const float* __restrict__ bias, float* __restrict__ C,
    int M, int Kp, int Nc) {
    extern __shared__ __nv_bfloat16 sm[];
    __shared__ float s_st[512];
    uint32_t sb = smem_u32(sm);
    int tid  = threadIdx.x;
    int lane = tid & 31;
    int w    = tid >> 5;
    int wr   = w & 1;
    int wc   = w >> 1;
    int row0 = blockIdx.y * 128;
    int col0 = blockIdx.x * 128;

    if (EPI == 1 && blockIdx.x == 0 && blockIdx.y == 0 && tid < 256) {
        g_sum[tid] = 0.f; g_sumsq[tid] = 0.f;
    }
    if (EPI == 3) { s_st[tid] = 0.f; s_st[tid + 256] = 0.f; }

    float acc[4][4][4];
#pragma unroll
    for (int i = 0; i < 4; i++)
#pragma unroll
        for (int j = 0; j < 4; j++)
#pragma unroll
            for (int q = 0; q < 4; q++) acc[i][j][q] = 0.f;

    const int nch = Kp >> 6;

    auto issue = [&](int c) {
        if (c < nch) {
            int stage = c % 3;
            uint32_t sA = sb + (uint32_t)stage * 32768u;
            uint32_t sB = sA + 16384u;
            int k0 = c << 6;
#pragma unroll
            for (int p = 0; p < 4; p++) {
                int idx = tid + (p << 8);
                int row = idx >> 3, u = idx & 7;
                uint32_t soff = SMEM_SWZ((uint32_t)(row * 128 + u * 16));
                int gr = row0 + row;
                cp_cg(sA + soff, A + (size_t)gr * Kp + k0 + u * 8, gr < M ? 16 : 0);
                cp_cg(sB + soff, BT + (size_t)(col0 + row) * Kp + k0 + u * 8, 16);
            }
        }
        CP_COMMIT();
    };
    auto compute = [&](int c) {
        int stage = c % 3;
        uint32_t bA = sb + (uint32_t)stage * 32768u;
        uint32_t bB = bA + 16384u;
#pragma unroll
        for (int ks = 0; ks < 4; ks++) {
            uint32_t a[4][4], b[4][2];
#pragma unroll
            for (int mi = 0; mi < 4; mi++) {
                uint32_t byte = (uint32_t)((wr * 64 + mi * 16 + (lane & 15)) * 128 +
                                           ks * 32 + ((lane >> 4) << 4));
                LDSM_X4(a[mi][0], a[mi][1], a[mi][2], a[mi][3], bA + SMEM_SWZ(byte));
            }
#pragma unroll
            for (int ni = 0; ni < 4; ni++) {
                uint32_t byte = (uint32_t)((wc * 32 + ni * 8 + (lane & 7)) * 128 +
                                           ks * 32 + (((lane >> 3) & 1) << 4));
                LDSM_X2(b[ni][0], b[ni][1], bB + SMEM_SWZ(byte));
            }
#pragma unroll
            for (int mi = 0; mi < 4; mi++)
#pragma unroll
                for (int ni = 0; ni < 4; ni++)
                    MMA16816(acc[mi][ni], a[mi][0], a[mi][1], a[mi][2], a[mi][3],
                             b[ni][0], b[ni][1]);
        }
    };

    issue(0);
    issue(1);
    for (int c = 0; c < nch; c++) {
        asm volatile("cp.async.wait_group 1;" ::: "memory");
        __syncthreads();
        issue(c + 2);
        compute(c);
    }

    float cs[4][2], cq[4][2];
    if (EPI == 3) {
#pragma unroll
        for (int ni = 0; ni < 4; ni++) {
            cs[ni][0] = cs[ni][1] = 0.f;
            cq[ni][0] = cq[ni][1] = 0.f;
        }
    }

#pragma unroll
    for (int mi = 0; mi < 4; mi++) {
#pragma unroll
        for (int ni = 0; ni < 4; ni++) {
            int r = row0 + wr * 64 + mi * 16 + (lane >> 2);
            int c = col0 + wc * 32 + ni * 8 + (lane & 3) * 2;
            float v0 = acc[mi][ni][0], v1 = acc[mi][ni][1];
            float v2 = acc[mi][ni][2], v3 = acc[mi][ni][3];
            if (EPI == 1) {
                float b0 = bias[c], b1 = bias[c + 1];
                v0 = fmaxf(v0 + b0, 0.f); v1 = fmaxf(v1 + b1, 0.f);
                v2 = fmaxf(v2 + b0, 0.f); v3 = fmaxf(v3 + b1, 0.f);
                __nv_bfloat16* P = g_Fpk;
#pragma unroll
                for (int hh = 0; hh < 2; hh++) {
                    int rr = r + hh * 8;
                    if (rr >= M) continue;
                    float u0 = hh ? v2 : v0, u1 = hh ? v3 : v1;
                    size_t base = (size_t)rr * 3072 + c;
                    __nv_bfloat162 hp = __floats2bfloat162_rn(u0, u1);
                    __nv_bfloat162 lp = __floats2bfloat162_rn(
                        u0 - __bfloat162float(hp.x), u1 - __bfloat162float(hp.y));
                    *(__nv_bfloat162*)&P[base]        = hp;
                    *(__nv_bfloat162*)&P[base + 1024] = lp;
                    *(__nv_bfloat162*)&P[base + 2048] = hp;
                }
            } else if (EPI == 2) {
                if (r < M)
                    *(__half2*)(g_xlrh + (size_t)r * 512 + c) = __floats2half2_rn(v0, v1);
                if (r + 8 < M)
                    *(__half2*)(g_xlrh + (size_t)(r + 8) * 512 + c) = __floats2half2_rn(v2, v3);
            } else {
                if (r < M) {
                    C[(size_t)r * Nc + c] = v0;
                    C[(size_t)r * Nc + c + 1] = v1;
                    if (EPI == 3) {
                        cs[ni][0] += v0; cq[ni][0] += v0 * v0;
                        cs[ni][1] += v1; cq[ni][1] += v1 * v1;
                    }
                }
                if (r + 8 < M) {
                    C[(size_t)(r + 8) * Nc + c] = v2;
                    C[(size_t)(r + 8) * Nc + c + 1] = v3;
                    if (EPI == 3) {
                        cs[ni][0] += v2; cq[ni][0] += v2 * v2;
                        cs[ni][1] += v3; cq[ni][1] += v3 * v3;
                    }
                }
            }
        }
    }
    if (EPI == 3) {
        __syncthreads();
#pragma unroll
        for (int ni = 0; ni < 4; ni++) {
            int gc = col0 + wc * 32 + ni * 8 + (lane & 3) * 2;
            atomicAdd(&s_st[gc],       cs[ni][0]);
            atomicAdd(&s_st[gc + 1],   cs[ni][1]);
            atomicAdd(&s_st[256 + gc],     cq[ni][0]);
            atomicAdd(&s_st[256 + gc + 1], cq[ni][1]);
        }
        __syncthreads();
        if (tid < 256) {
            atomicAdd(&g_sum[tid],   s_st[tid]);
            atomicAdd(&g_sumsq[tid], s_st[tid + 256]);
        }
    }
}

// ---------------- ee GEMM (Kp=64, x2 pack, CSR-ordered) + GATv2 score -----------
#define SC_SMEM 55296

__global__ void __launch_bounds__(512, 1) gemm_score(
    const __nv_bfloat16* __restrict__ A, const __nv_bfloat16* __restrict__ BT,
    const float* __restrict__ att) {
    extern __shared__ char smc[];
    uint32_t sb = smem_u32(smc);
    float* sc_s  = (float*)(smc + 49152);
    float* att_s = (float*)(smc + 53248);
    int*   ss_s  = (int*)(smc + 54272);
    int*   sd_s  = (int*)(smc + 54784);
    int tid = threadIdx.x, lane = tid & 31, w = tid >> 5;
    int wr = w & 3, wc = w >> 2;
    int row0 = blockIdx.x * 128;

    if (blockIdx.x == 0 && tid < 256) { g_sum[tid] = 0.f; g_sumsq[tid] = 0.f; }

    if (tid < 256) att_s[tid] = att[tid];
    if (tid < 128) {
        int e = row0 + tid;                    // CSR position
        int s, d;
        if (e < Ee)       { s = g_adj[e].x; d = g_pdst[e]; }
        else if (e < ETOT){ s = e - Ee; d = s; }
        else              { s = 0; d = 0; }
        ss_s[tid] = s; sd_s[tid] = d;
    }
#pragma unroll
    for (int p = 0; p < 2; p++) {
        int j = tid + (p << 9);
        int row = j >> 3, u = j & 7;
        uint32_t soff = SMEM_SWZ((uint32_t)(row * 128 + u * 16));
        int gr = row0 + row;
        cp_cg(sb + soff, A + (size_t)gr * 64 + u * 8, gr < ETOT ? 16 : 0);
    }
#pragma unroll
    for (int p = 0; p < 4; p++) {
        int j = tid + (p << 9);
        int row = j >> 3, u = j & 7;
        uint32_t soff = 16384u + SMEM_SWZ((uint32_t)(row * 128 + u * 16));
        cp_cg(sb + soff, BT + (size_t)row * 64 + u * 8, 16);
    }
    CP_COMMIT();
    asm volatile("cp.async.wait_group 0;" ::: "memory");
    __syncthreads();

    float acc[2][8][4];
#pragma unroll
    for (int i = 0; i < 2; i++)
#pragma unroll
        for (int j = 0; j < 8; j++)
#pragma unroll
            for (int q = 0; q < 4; q++) acc[i][j][q] = 0.f;

    uint32_t bA = sb;
    uint32_t bB = sb + 16384u;
#pragma unroll
    for (int ks = 0; ks < 4; ks++) {
        uint32_t a[2][4], b[8][2];
#pragma unroll
        for (int mi = 0; mi < 2; mi++) {
            uint32_t byte = (uint32_t)((wr * 32 + mi * 16 + (lane & 15)) * 128 +
                                       ks * 32 + ((lane >> 4) << 4));
            LDSM_X4(a[mi][0], a[mi][1], a[mi][2], a[mi][3], bA + SMEM_SWZ(byte));
        }
#pragma unroll
        for (int ni = 0; ni < 8; ni++) {
            uint32_t byte = (uint32_t)((wc * 64 + ni * 8 + (lane & 7)) * 128 +
                                       ks * 32 + (((lane >> 3) & 1) << 4));
            LDSM_X2(b[ni][0], b[ni][1], bB + SMEM_SWZ(byte));
        }
#pragma unroll
        for (int mi = 0; mi < 2; mi++)
#pragma unroll
            for (int ni = 0; ni < 8; ni++)
                MMA16816(acc[mi][ni], a[mi][0], a[mi][1], a[mi][2], a[mi][3],
                         b[ni][0], b[ni][1]);
    }

#pragma unroll
    for (int mi = 0; mi < 2; mi++) {
#pragma unroll
        for (int hf = 0; hf < 2; hf++) {
            int r = wr * 32 + mi * 16 + (lane >> 2) + hf * 8;
            int s = ss_s[r], d = sd_s[r];
            const __half* xlp = g_xlrh + (size_t)s * 512;
            const __half* xrp = g_xlrh + (size_t)d * 512 + 256;
            float h0 = 0.f, h1 = 0.f;
#pragma unroll
            for (int ni = 0; ni < 8; ni++) {
                int c0 = wc * 64 + ni * 8 + (lane & 3) * 2;
                float2 xlv = __half22float2(*(const __half2*)(xlp + c0));
                float2 xrv = __half22float2(*(const __half2*)(xrp + c0));
                float z0 = acc[mi][ni][hf * 2 + 0] + xlv.x + xrv.x;
                float z1 = acc[mi][ni][hf * 2 + 1] + xlv.y + xrv.y;
                z0 = (z0 > 0.f) ? z0 : 0.2f * z0;
                z1 = (z1 > 0.f) ? z1 : 0.2f * z1;
                float pp = z0 * att_s[c0] + z1 * att_s[c0 + 1];
                if (ni < 4) h0 += pp; else h1 += pp;
            }
            h0 += __shfl_xor_sync(0xffffffffu, h0, 1);
            h0 += __shfl_xor_sync(0xffffffffu, h0, 2);
            h1 += __shfl_xor_sync(0xffffffffu, h1, 1);
            h1 += __shfl_xor_sync(0xffffffffu, h1, 2);
            if ((lane & 3) == 0) {
                sc_s[r * 8 + wc * 2]     = h0;
                sc_s[r * 8 + wc * 2 + 1] = h1;
            }
        }
    }
    __syncthreads();
#pragma unroll
    for (int p = 0; p < 2; p++) {
        int i = tid + (p << 9);
        int r = i >> 3;
        int e = row0 + r;
        if (e < ETOT) g_sc[(size_t)e * 8 + (i & 7)] = sc_s[i];
    }
}

// ---------------- CSR build ------------------------------------------------------
__global__ void k_zero_icnt() {
    int i = blockIdx.x * blockDim.x + threadIdx.x;
    if (i < Nn) g_icnt[i] = 0;
}
__global__ void k_count(const int* __restrict__ dst) {
    int e = blockIdx.x * blockDim.x + threadIdx.x;
    if (e < Ee) atomicAdd(&g_icnt[dst[e]], 1);
}
__global__ void k_scan() {
    __shared__ int part[1024];
    int t = threadIdx.x;
    const int SEG = (Nn + 1023) / 1024;
    int base = t * SEG;
    int s = 0;
    for (int i = 0; i < SEG; i++) {
        int idx = base + i;
        if (idx < Nn) s += g_icnt[idx];
    }
    part[t] = s;
    __syncthreads();
    for (int off = 1; off < 1024; off <<= 1) {
        int v = (t >= off) ? part[t - off] : 0;
        __syncthreads();
        part[t] += v;
        __syncthreads();
    }
    int run = (t == 0) ? 0 : part[t - 1];
    for (int i = 0; i < SEG; i++) {
        int idx = base + i;
        if (idx < Nn) {
            g_rowptr[idx] = run;
            g_tmp[idx] = run;
            run += g_icnt[idx];
        }
    }
    if (t == 1023) g_rowptr[Nn] = run;
}
__global__ void k_scatter(const int* __restrict__ src, const int* __restrict__ dst) {
    int e = blockIdx.x * blockDim.x + threadIdx.x;
    if (e >= Ee) return;
    int d = dst[e];
    int pos = atomicAdd(&g_tmp[d], 1);
    g_adj[pos] = make_int2(src[e], e);
    g_pdst[pos] = d;
}
__global__ void k_loop_mean(const float* __restrict__ ew) {
    int d    = blockIdx.x * 8 + (threadIdx.x >> 5);
    int lane = threadIdx.x & 31;
    if (d >= Nn) return;
    int beg = g_rowptr[d], end = g_rowptr[d + 1];
    float s = 0.f;
    for (int i = beg; i < end; i++)
        s += ew[(size_t)g_adj[i].y * EDIMc + lane];
    g_loop[(size_t)d * EDIMc + lane] = s / fmaxf((float)(end - beg), 1.f);
}

// ---------------- per-node softmax + aggregation (fp16 gather, CSR scores) ------
__device__ __forceinline__ void acc_h8(float* acc, const __half* xp, float w) {
    uint4 raw = *(const uint4*)xp;
    const __half2* hp = (const __half2*)&raw;
    float2 f0 = __half22float2(hp[0]);
    float2 f1 = __half22float2(hp[1]);
    float2 f2 = __half22float2(hp[2]);
    float2 f3 = __half22float2(hp[3]);
    acc[0] += w * f0.x; acc[1] += w * f0.y;
    acc[2] += w * f1.x; acc[3] += w * f1.y;
    acc[4] += w * f2.x; acc[5] += w * f2.y;
    acc[6] += w * f3.x; acc[7] += w * f3.y;
}
__global__ void k_node() {
    __shared__ float s_st[512];
    int tid  = threadIdx.x;
    int d    = blockIdx.x * 8 + (tid >> 5);
    int lane = tid & 31;
    s_st[tid] = 0.f;
    s_st[tid + 256] = 0.f;
    __syncthreads();

    int beg = g_rowptr[d], end = g_rowptr[d + 1];
    const float* ssc = g_sc + (size_t)(Ee + d) * Hh;

    int hh = lane >> 2;
    int c0 = lane << 3;

    float den;
    float acc[8];
#pragma unroll
    for (int q = 0; q < 8; q++) acc[q] = 0.f;
    {
        float a = __expf(ssc[hh]);
        den = a;
        acc_h8(acc, g_xlrh + (size_t)d * 512 + c0, a);
    }
    int i = beg;
    for (; i + 1 < end; i += 2) {
        int s0i = g_adj[i].x, s1i = g_adj[i + 1].x;
        float s0 = g_sc[(size_t)i * Hh + hh];
        float s1 = g_sc[(size_t)(i + 1) * Hh + hh];
        float w0 = __expf(s0), w1 = __expf(s1);
        den += w0 + w1;
        acc_h8(acc, g_xlrh + (size_t)s0i * 512 + c0, w0);
        acc_h8(acc, g_xlrh + (size_t)s1i * 512 + c0, w1);
    }
    if (i < end) {
        int s0i = g_adj[i].x;
        float w0 = __expf(g_sc[(size_t)i * Hh + hh]);
        den += w0;
        acc_h8(acc, g_xlrh + (size_t)s0i * 512 + c0, w0);
    }
    float inv = 1.f / den;
#pragma unroll
    for (int q = 0; q < 8; q++) acc[q] *= inv;

    float4* op = (float4*)(g_agg + (size_t)d * DIMc + c0);
    op[0] = make_float4(acc[0], acc[1], acc[2], acc[3]);
    op[1] = make_float4(acc[4], acc[5], acc[6], acc[7]);

#pragma unroll
    for (int q = 0; q < 8; q++) {
        atomicAdd(&s_st[c0 + q], acc[q]);
        atomicAdd(&s_st[256 + c0 + q], acc[q] * acc[q]);
    }
    __syncthreads();
    if (tid < 256) {
        atomicAdd(&g_sum[tid], s_st[tid]);
        atomicAdd(&g_sumsq[tid], s_st[tid + 256]);
    }
}

// ---------------- BatchNorm apply (vectorized, 4 cols/thread) --------------------
template<bool PACK>
__global__ void k_bnapply(const float* __restrict__ X, const float* __restrict__ gam,
                          const float* __restrict__ bet, const float* __restrict__ res,
                          float* __restrict__ out) {
    int i4 = blockIdx.x * blockDim.x + threadIdx.x;
    if (i4 >= Nn * DIMc / 4) return;
    int i = i4 << 2;
    int c = i & (DIMc - 1);
    float4 xv = *(const float4*)&X[i];
    float4 rv = *(const float4*)&res[i];
    float vo[4];
    float xs[4] = {xv.x, xv.y, xv.z, xv.w};
    float rs[4] = {rv.x, rv.y, rv.z, rv.w};
#pragma unroll
    for (int q = 0; q < 4; q++) {
        int cc = c + q;
        float mu  = g_sum[cc]   * (1.f / Nn);
        float var = g_sumsq[cc] * (1.f / Nn) - mu * mu;
        float y = (xs[q] - mu) * rsqrtf(var + 1e-5f) * gam[cc] + bet[cc];
        y = (y > 0.f) ? y : 0.01f * y;
        vo[q] = rs[q] + y;
    }
    *(float4*)&out[i] = make_float4(vo[0], vo[1], vo[2], vo[3]);
    if (PACK) {
        int r = i >> 8;
        size_t b = (size_t)r * 768 + c;
        __nv_bfloat162 h0 = __floats2bfloat162_rn(vo[0], vo[1]);
        __nv_bfloat162 h1 = __floats2bfloat162_rn(vo[2], vo[3]);
        __nv_bfloat162 l0 = __floats2bfloat162_rn(vo[0] - __bfloat162float(h0.x),
                                                  vo[1] - __bfloat162float(h0.y));
        __nv_bfloat162 l1 = __floats2bfloat162_rn(vo[2] - __bfloat162float(h1.x),
                                                  vo[3] - __bfloat162float(h1.y));
        *(__nv_bfloat162*)&g_Apk[b]           = h0;
        *(__nv_bfloat162*)&g_Apk[b + 2]       = h1;
        *(__nv_bfloat162*)&g_Apk[b + 256]     = l0;
        *(__nv_bfloat162*)&g_Apk[b + 258]     = l1;
        *(__nv_bfloat162*)&g_Apk[b + 512]     = h0;
        *(__nv_bfloat162*)&g_Apk[b + 514]     = h1;
    }
}

// ---------------- host orchestration ----------------------------------------------
static inline int cdiv(int a, int b) { return (a + b - 1) / b; }

extern "C" void kernel_launch(void* const* d_in, const int* in_sizes, int n_in,
                              void* d_out, int out_size) {
    const float* nf    = (const float*)d_in[0];
    const int*   ei    = (const int*)  d_in[1];
    const float* ew    = (const float*)d_in[2];
    const float* g1_Wl = (const float*)d_in[3];
    const float* g1_Wr = (const float*)d_in[4];
    const float* g1_We = (const float*)d_in[5];
    const float* g1_at = (const float*)d_in[6];
    const float* g2_Wl = (const float*)d_in[8];
    const float* g2_Wr = (const float*)d_in[9];
    const float* g2_We = (const float*)d_in[10];
    const float* g2_at = (const float*)d_in[11];
    const float* n1_g  = (const float*)d_in[13];
    const float* n1_b  = (const float*)d_in[14];
    const float* n2_g  = (const float*)d_in[15];
    const float* n2_b  = (const float*)d_in[16];
    const float* n3_g  = (const float*)d_in[17];
    const float* n3_b  = (const float*)d_in[18];
    const float* ff_W1 = (const float*)d_in[19];
    const float* ff_b1 = (const float*)d_in[20];
    const float* ff_W2 = (const float*)d_in[21];
    const int* src = ei;
    const int* dst = ei + Ee;
    float* out = (float*)d_out;

    void* p;
    cudaGetSymbolAddress(&p, g_agg);  float* agg  = (float*)p;
    cudaGetSymbolAddress(&p, g_h1);   float* h1   = (float*)p;
    cudaGetSymbolAddress(&p, g_h2);   float* h2   = (float*)p;
    cudaGetSymbolAddress(&p, g_ff2);  float* ff2  = (float*)p;
    cudaGetSymbolAddress(&p, g_Apk);  __nv_bfloat16* Apk = (__nv_bfloat16*)p;
    cudaGetSymbolAddress(&p, g_Fpk);  __nv_bfloat16* Fpk = (__nv_bfloat16*)p;
    cudaGetSymbolAddress(&p, g_EApk); __nv_bfloat16* EApk = (__nv_bfloat16*)p;
    cudaGetSymbolAddress(&p, g_Wpk);  __nv_bfloat16* Wpk = (__nv_bfloat16*)p;

    cudaFuncSetAttribute(gemm_pk<0>, cudaFuncAttributeMaxDynamicSharedMemorySize, GEMM_SMEM_PK);
    cudaFuncSetAttribute(gemm_pk<1>, cudaFuncAttributeMaxDynamicSharedMemorySize, GEMM_SMEM_PK);
    cudaFuncSetAttribute(gemm_pk<2>, cudaFuncAttributeMaxDynamicSharedMemorySize, GEMM_SMEM_PK);
    cudaFuncSetAttribute(gemm_pk<3>, cudaFuncAttributeMaxDynamicSharedMemorySize, GEMM_SMEM_PK);
    cudaFuncSetAttribute(gemm_score, cudaFuncAttributeMaxDynamicSharedMemorySize, SC_SMEM);

    cudaStream_t sd = 0;
    cudaEvent_t ev0 = nullptr, ev1 = nullptr;
    cudaStreamCreateWithFlags(&sd, cudaStreamNonBlocking);
    cudaEventCreateWithFlags(&ev0, cudaEventDisableTiming);
    cudaEventCreateWithFlags(&ev1, cudaEventDisableTiming);

    // ---- fork: CSR + edge-attr chain on side stream ----
    cudaEventRecord(ev0, 0);
    cudaStreamWaitEvent(sd, ev0, 0);
    k_zero_icnt<<<cdiv(Nn, 256), 256, 0, sd>>>();
    k_count<<<cdiv(Ee, 256), 256, 0, sd>>>(dst);
    k_scan<<<1, 1024, 0, sd>>>();
    k_scatter<<<cdiv(Ee, 256), 256, 0, sd>>>(src, dst);
    k_loop_mean<<<cdiv(Nn, 8), 256, 0, sd>>>(ew);
    k_pack_ea<<<cdiv(ETOT * EDIMc, 256), 256, 0, sd>>>(ew);
    cudaEventRecord(ev1, sd);

    // ---- main stream: weight packs, node pack, xlr GEMM ----
    k_packT_all<<<cdiv(802816, 256), 256>>>(g1_Wl, g1_Wr, g1_We, g2_Wl, g2_Wr, g2_We,
                                            ff_W1, ff_W2, Wpk);
    k_pack_node<<<cdiv(Nn * DIMc, 256), 256>>>(nf, Apk, Nn, DIMc);

    dim3 gXLR(4, cdiv(Nn, 128));
    int nbScore = cdiv(ETOT, 128);
    int nbNode  = cdiv(Nn, 8);

    gemm_pk<2><<<gXLR, 256, GEMM_SMEM_PK>>>(Apk, Wpk + OWLR1, nullptr, nullptr, Nn, 768, 512);

    // ---- join ----
    cudaStreamWaitEvent(0, ev1, 0);

    // ---- block 1 ----
    gemm_score<<<nbScore, 512, SC_SMEM>>>(EApk, Wpk + OWE1, g1_at);
    k_node<<<nbNode, 256>>>();
    k_bnapply<true><<<cdiv(Nn * DIMc / 4, 256), 256>>>(agg, n1_g, n1_b, nf, h1);

    // ---- block 2 ----
    gemm_pk<2><<<gXLR, 256, GEMM_SMEM_PK>>>(Apk, Wpk + OWLR2, nullptr, nullptr, Nn, 768, 512);
    gemm_score<<<nbScore, 512, SC_SMEM>>>(EApk, Wpk + OWE2, g2_at);
    k_node<<<nbNode, 256>>>();
    k_bnapply<true><<<cdiv(Nn * DIMc / 4, 256), 256>>>(agg, n2_g, n2_b, h1, h2);

    // ---- feed-forward ----
    dim3 gF1(8, cdiv(Nn, 128));
    gemm_pk<1><<<gF1, 256, GEMM_SMEM_PK>>>(Apk, Wpk + OW1, ff_b1, nullptr, Nn, 768, DFFc);
    dim3 gF2(2, cdiv(Nn, 128));
    gemm_pk<3><<<gF2, 256, GEMM_SMEM_PK>>>(Fpk, Wpk + OW2, nullptr, ff2, Nn, 3072, DIMc);
    k_bnapply<false><<<cdiv(Nn * DIMc / 4, 256), 256>>>(ff2, n3_g, n3_b, h2, out);
}

// round 17
// speedup vs baseline: 1.1184x; 1.0074x over previous
#include <cuda_runtime.h>
#include <cuda_bf16.h>
#include <cuda_fp16.h>
#include <math.h>
#include <stdint.h>

#define Nn    20000
#define Ee    320000
#define DIMc  256
#define Hh    8
#define EDIMc 32
#define DFFc  1024
#define ETOT  (Ee + Nn)

// ---------------- scratch (device globals) -----------------------------------
static __device__ __half   g_xlrh[(size_t)Nn * 512];     // fp16 [xl | xr] (only copy)
static __device__ float    g_loop[(size_t)Nn * EDIMc];
static __device__ int      g_icnt[Nn];
static __device__ float    g_sc [(size_t)ETOT * Hh];     // exp(score), CSR position
static __device__ float    g_agg[(size_t)Nn * DIMc];
static __device__ float    g_h1 [(size_t)Nn * DIMc];
static __device__ float    g_h2 [(size_t)Nn * DIMc];
static __device__ float    g_ff2[(size_t)Nn * DIMc];
static __device__ float    g_sum[DIMc];
static __device__ float    g_sumsq[DIMc];
static __device__ int      g_rowptr[Nn + 1];
static __device__ int      g_tmp[Nn];
static __device__ int2     g_adj[Ee];                    // {src, edge_id} per CSR pos
static __device__ int      g_pdst[Ee];                   // dst per CSR pos

static __device__ __nv_bfloat16 g_Apk[(size_t)Nn * 768];
static __device__ __nv_bfloat16 g_Fpk[(size_t)Nn * 3072];
static __device__ __nv_bfloat16 g_EApk[(size_t)ETOT * 64];   // CSR-ordered [Ah|Al]
#define OWLR1 0
#define OWE1  393216
#define OWLR2 409600
#define OWE2  802816
#define OW1   819200
#define OW2   1605632
#define WPK_TOTAL 2392064
static __device__ __nv_bfloat16 g_Wpk[WPK_TOTAL];

// ---------------- PTX helpers --------------------------------------------------
__device__ __forceinline__ uint32_t smem_u32(const void* p) {
    uint32_t a;
    asm("{ .reg .u64 t; cvta.to.shared.u64 t, %1; cvt.u32.u64 %0, t; }"
        : "=r"(a) : "l"(p));
    return a;
}
#define LDSM_X4(r0, r1, r2, r3, addr) \
    asm volatile("ldmatrix.sync.aligned.m8n8.x4.shared.b16 {%0,%1,%2,%3}, [%4];" \
                 : "=r"(r0), "=r"(r1), "=r"(r2), "=r"(r3) : "r"(addr))
#define LDSM_X2(r0, r1, addr) \
    asm volatile("ldmatrix.sync.aligned.m8n8.x2.shared.b16 {%0,%1}, [%2];" \
                 : "=r"(r0), "=r"(r1) : "r"(addr))
#define MMA16816(c, a0, a1, a2, a3, b0, b1) \
    asm volatile("mma.sync.aligned.m16n8k16.row.col.f32.bf16.bf16.f32 " \
                 "{%0,%1,%2,%3}, {%4,%5,%6,%7}, {%8,%9}, {%0,%1,%2,%3};" \
                 : "+f"((c)[0]), "+f"((c)[1]), "+f"((c)[2]), "+f"((c)[3]) \
                 : "r"(a0), "r"(a1), "r"(a2), "r"(a3), "r"(b0), "r"(b1))
__device__ __forceinline__ void cp_cg(uint32_t dst, const void* src, int sz) {
    asm volatile("cp.async.cg.shared.global [%0], [%1], 16, %2;"
                 :: "r"(dst), "l"(src), "r"(sz));
}
#define CP_COMMIT() asm volatile("cp.async.commit_group;" ::: "memory")
#define SMEM_SWZ(b) ((b) ^ (((b) >> 3) & 0x70))

// ---------------- pack kernels --------------------------------------------------
__global__ void k_pack_node(const float* __restrict__ X, __nv_bfloat16* __restrict__ A,
                            int rows, int K) {
    int i = blockIdx.x * blockDim.x + threadIdx.x;
    if (i >= rows * K) return;
    int r = i / K, k = i - r * K;
    float v = X[i];
    __nv_bfloat16 h = __float2bfloat16(v);
    __nv_bfloat16 l = __float2bfloat16(v - __bfloat162float(h));
    size_t b = (size_t)r * (3 * K);
    A[b + k] = h;
    A[b + K + k] = l;
    A[b + 2 * K + k] = h;
}
__global__ void k_pack_ea(const float* __restrict__ ew) {
    int i = blockIdx.x * blockDim.x + threadIdx.x;
    if (i >= ETOT * EDIMc) return;
    int r = i >> 5, k = i & 31;
    float v;
    if (r < Ee) {
        int eid = g_adj[r].y;
        v = ew[(size_t)eid * EDIMc + k];
    } else {
        v = g_loop[(size_t)(r - Ee) * EDIMc + k];
    }
    __nv_bfloat16 h = __float2bfloat16(v);
    __nv_bfloat16 l = __float2bfloat16(v - __bfloat162float(h));
    size_t b = (size_t)r * 64;
    g_EApk[b + k]      = h;
    g_EApk[b + 32 + k] = l;
}
__device__ __forceinline__ void pack_w_one(const float* __restrict__ W,
                                           __nv_bfloat16* __restrict__ WT,
                                           int i, int K, int N, int Kp) {
    int k = i / N, n = i - k * N;
    float v = W[i];
    __nv_bfloat16 h = __float2bfloat16(v);
    __nv_bfloat16 l = __float2bfloat16(v - __bfloat162float(h));
    size_t b = (size_t)n * Kp;
    WT[b + k]         = h;
    WT[b + K + k]     = h;
    WT[b + 2 * K + k] = l;
    if (k < Kp - 3 * K) WT[b + 3 * K + k] = __float2bfloat16(0.f);
}
__device__ __forceinline__ void pack_w_x2(const float* __restrict__ W,
                                          __nv_bfloat16* __restrict__ WT, int i) {
    int k = i >> 8, n = i & 255;
    __nv_bfloat16 h = __float2bfloat16(W[i]);
    WT[n * 64 + k]      = h;
    WT[n * 64 + 32 + k] = h;
}
__global__ void k_packT_all(const float* w0, const float* w1, const float* w2,
                            const float* w3, const float* w4, const float* w5,
                            const float* w6, const float* w7,
                            __nv_bfloat16* __restrict__ WT) {
    int i = blockIdx.x * blockDim.x + threadIdx.x;
    if (i < 65536)        pack_w_one(w0, WT + OWLR1,          i,           DIMc, DIMc, 768);
    else if (i < 131072)  pack_w_one(w1, WT + OWLR1 + 196608, i - 65536,   DIMc, DIMc, 768);
    else if (i < 139264)  pack_w_x2 (w2, WT + OWE1,           i - 131072);
    else if (i < 204800)  pack_w_one(w3, WT + OWLR2,          i - 139264,  DIMc, DIMc, 768);
    else if (i < 270336)  pack_w_one(w4, WT + OWLR2 + 196608, i - 204800,  DIMc, DIMc, 768);
    else if (i < 278528)  pack_w_x2 (w5, WT + OWE2,           i - 270336);
    else if (i < 540672)  pack_w_one(w6, WT + OW1,            i - 278528,  DIMc, DFFc, 768);
    else if (i < 802816)  pack_w_one(w7, WT + OW2,            i - 540672,  DFFc, DIMc, 3072);
}

// ---------------- 3-stage pipelined bf16 GEMM (K-packed x3) --------------------
#define GEMM_SMEM_PK 98304

template<int EPI>
__global__ void __launch_bounds__(256, 2) gemm_pk(
    const __nv_bfloat16* __restrict__ A, const __nv_bfloat16* __restrict__ BT,
    const float* __restrict__ bias, float* __restrict__ C,
    int M, int Kp, int Nc) {
    extern __shared__ __nv_bfloat16 sm[];
    __shared__ float s_st[512];
    uint32_t sb = smem_u32(sm);
    int tid  = threadIdx.x;
    int lane = tid & 31;
    int w    = tid >> 5;
    int wr   = w & 1;
    int wc   = w >> 1;
    int row0 = blockIdx.y * 128;
    int col0 = blockIdx.x * 128;

    if (EPI == 1 && blockIdx.x == 0 && blockIdx.y == 0 && tid < 256) {
        g_sum[tid] = 0.f; g_sumsq[tid] = 0.f;
    }
    if (EPI == 3) { s_st[tid] = 0.f; s_st[tid + 256] = 0.f; }

    float acc[4][4][4];
#pragma unroll
    for (int i = 0; i < 4; i++)
#pragma unroll
        for (int j = 0; j < 4; j++)
#pragma unroll
            for (int q = 0; q < 4; q++) acc[i][j][q] = 0.f;

    const int nch = Kp >> 6;

    auto issue = [&](int c) {
        if (c < nch) {
            int stage = c % 3;
            uint32_t sA = sb + (uint32_t)stage * 32768u;
            uint32_t sB = sA + 16384u;
            int k0 = c << 6;
#pragma unroll
            for (int p = 0; p < 4; p++) {
                int idx = tid + (p << 8);
                int row = idx >> 3, u = idx & 7;
                uint32_t soff = SMEM_SWZ((uint32_t)(row * 128 + u * 16));
                int gr = row0 + row;
                cp_cg(sA + soff, A + (size_t)gr * Kp + k0 + u * 8, gr < M ? 16 : 0);
                cp_cg(sB + soff, BT + (size_t)(col0 + row) * Kp + k0 + u * 8, 16);
            }
        }
        CP_COMMIT();
    };
    auto compute = [&](int c) {
        int stage = c % 3;
        uint32_t bA = sb + (uint32_t)stage * 32768u;
        uint32_t bB = bA + 16384u;
#pragma unroll
        for (int ks = 0; ks < 4; ks++) {
            uint32_t a[4][4], b[4][2];
#pragma unroll
            for (int mi = 0; mi < 4; mi++) {
                uint32_t byte = (uint32_t)((wr * 64 + mi * 16 + (lane & 15)) * 128 +
                                           ks * 32 + ((lane >> 4) << 4));
                LDSM_X4(a[mi][0], a[mi][1], a[mi][2], a[mi][3], bA + SMEM_SWZ(byte));
            }
#pragma unroll
            for (int ni = 0; ni < 4; ni++) {
                uint32_t byte = (uint32_t)((wc * 32 + ni * 8 + (lane & 7)) * 128 +
                                           ks * 32 + (((lane >> 3) & 1) << 4));
                LDSM_X2(b[ni][0], b[ni][1], bB + SMEM_SWZ(byte));
            }
#pragma unroll
            for (int mi = 0; mi < 4; mi++)
#pragma unroll
                for (int ni = 0; ni < 4; ni++)
                    MMA16816(acc[mi][ni], a[mi][0], a[mi][1], a[mi][2], a[mi][3],
                             b[ni][0], b[ni][1]);
        }
    };

    issue(0);
    issue(1);
    for (int c = 0; c < nch; c++) {
        asm volatile("cp.async.wait_group 1;" ::: "memory");
        __syncthreads();
        issue(c + 2);
        compute(c);
    }

    float cs[4][2], cq[4][2];
    if (EPI == 3) {
#pragma unroll
        for (int ni = 0; ni < 4; ni++) {
            cs[ni][0] = cs[ni][1] = 0.f;
            cq[ni][0] = cq[ni][1] = 0.f;
        }
    }

#pragma unroll
    for (int mi = 0; mi < 4; mi++) {
#pragma unroll
        for (int ni = 0; ni < 4; ni++) {
            int r = row0 + wr * 64 + mi * 16 + (lane >> 2);
            int c = col0 + wc * 32 + ni * 8 + (lane & 3) * 2;
            float v0 = acc[mi][ni][0], v1 = acc[mi][ni][1];
            float v2 = acc[mi][ni][2], v3 = acc[mi][ni][3];
            if (EPI == 1) {
                float b0 = bias[c], b1 = bias[c + 1];
                v0 = fmaxf(v0 + b0, 0.f); v1 = fmaxf(v1 + b1, 0.f);
                v2 = fmaxf(v2 + b0, 0.f); v3 = fmaxf(v3 + b1, 0.f);
                __nv_bfloat16* P = g_Fpk;
#pragma unroll
                for (int hh = 0; hh < 2; hh++) {
                    int rr = r + hh * 8;
                    if (rr >= M) continue;
                    float u0 = hh ? v2 : v0, u1 = hh ? v3 : v1;
                    size_t base = (size_t)rr * 3072 + c;
                    __nv_bfloat162 hp = __floats2bfloat162_rn(u0, u1);
                    __nv_bfloat162 lp = __floats2bfloat162_rn(
                        u0 - __bfloat162float(hp.x), u1 - __bfloat162float(hp.y));
                    *(__nv_bfloat162*)&P[base]        = hp;
                    *(__nv_bfloat162*)&P[base + 1024] = lp;
                    *(__nv_bfloat162*)&P[base + 2048] = hp;
                }
            } else if (EPI == 2) {
                if (r < M)
                    *(__half2*)(g_xlrh + (size_t)r * 512 + c) = __floats2half2_rn(v0, v1);
                if (r + 8 < M)
                    *(__half2*)(g_xlrh + (size_t)(r + 8) * 512 + c) = __floats2half2_rn(v2, v3);
            } else {
                if (r < M) {
                    C[(size_t)r * Nc + c] = v0;
                    C[(size_t)r * Nc + c + 1] = v1;
                    if (EPI == 3) {
                        cs[ni][0] += v0; cq[ni][0] += v0 * v0;
                        cs[ni][1] += v1; cq[ni][1] += v1 * v1;
                    }
                }
                if (r + 8 < M) {
                    C[(size_t)(r + 8) * Nc + c] = v2;
                    C[(size_t)(r + 8) * Nc + c + 1] = v3;
                    if (EPI == 3) {
                        cs[ni][0] += v2; cq[ni][0] += v2 * v2;
                        cs[ni][1] += v3; cq[ni][1] += v3 * v3;
                    }
                }
            }
        }
    }
    if (EPI == 3) {
        __syncthreads();
#pragma unroll
        for (int ni = 0; ni < 4; ni++) {
            int gc = col0 + wc * 32 + ni * 8 + (lane & 3) * 2;
            atomicAdd(&s_st[gc],       cs[ni][0]);
            atomicAdd(&s_st[gc + 1],   cs[ni][1]);
            atomicAdd(&s_st[256 + gc],     cq[ni][0]);
            atomicAdd(&s_st[256 + gc + 1], cq[ni][1]);
        }
        __syncthreads();
        if (tid < 256) {
            atomicAdd(&g_sum[tid],   s_st[tid]);
            atomicAdd(&g_sumsq[tid], s_st[tid + 256]);
        }
    }
}

// ---------------- ee GEMM (Kp=64, x2 pack, CSR-ordered) + GATv2 score -----------
// g_sc receives exp(score): the __expf is hoisted here so k_node's inner loop has
// no MUFU on its dependent chain. Same fp32 inputs -> bit-identical alphas.
#define SC_SMEM 55296

__global__ void __launch_bounds__(512, 1) gemm_score(
    const __nv_bfloat16* __restrict__ A, const __nv_bfloat16* __restrict__ BT,
    const float* __restrict__ att) {
    extern __shared__ char smc[];
    uint32_t sb = smem_u32(smc);
    float* sc_s  = (float*)(smc + 49152);
    float* att_s = (float*)(smc + 53248);
    int*   ss_s  = (int*)(smc + 54272);
    int*   sd_s  = (int*)(smc + 54784);
    int tid = threadIdx.x, lane = tid & 31, w = tid >> 5;
    int wr = w & 3, wc = w >> 2;
    int row0 = blockIdx.x * 128;

    if (blockIdx.x == 0 && tid < 256) { g_sum[tid] = 0.f; g_sumsq[tid] = 0.f; }

    if (tid < 256) att_s[tid] = att[tid];
    if (tid < 128) {
        int e = row0 + tid;
        int s, d;
        if (e < Ee)       { s = g_adj[e].x; d = g_pdst[e]; }
        else if (e < ETOT){ s = e - Ee; d = s; }
        else              { s = 0; d = 0; }
        ss_s[tid] = s; sd_s[tid] = d;
    }
#pragma unroll
    for (int p = 0; p < 2; p++) {
        int j = tid + (p << 9);
        int row = j >> 3, u = j & 7;
        uint32_t soff = SMEM_SWZ((uint32_t)(row * 128 + u * 16));
        int gr = row0 + row;
        cp_cg(sb + soff, A + (size_t)gr * 64 + u * 8, gr < ETOT ? 16 : 0);
    }
#pragma unroll
    for (int p = 0; p < 4; p++) {
        int j = tid + (p << 9);
        int row = j >> 3, u = j & 7;
        uint32_t soff = 16384u + SMEM_SWZ((uint32_t)(row * 128 + u * 16));
        cp_cg(sb + soff, BT + (size_t)row * 64 + u * 8, 16);
    }
    CP_COMMIT();
    asm volatile("cp.async.wait_group 0;" ::: "memory");
    __syncthreads();

    float acc[2][8][4];
#pragma unroll
    for (int i = 0; i < 2; i++)
#pragma unroll
        for (int j = 0; j < 8; j++)
#pragma unroll
            for (int q = 0; q < 4; q++) acc[i][j][q] = 0.f;

    uint32_t bA = sb;
    uint32_t bB = sb + 16384u;
#pragma unroll
    for (int ks = 0; ks < 4; ks++) {
        uint32_t a[2][4], b[8][2];
#pragma unroll
        for (int mi = 0; mi < 2; mi++) {
            uint32_t byte = (uint32_t)((wr * 32 + mi * 16 + (lane & 15)) * 128 +
                                       ks * 32 + ((lane >> 4) << 4));
            LDSM_X4(a[mi][0], a[mi][1], a[mi][2], a[mi][3], bA + SMEM_SWZ(byte));
        }
#pragma unroll
        for (int ni = 0; ni < 8; ni++) {
            uint32_t byte = (uint32_t)((wc * 64 + ni * 8 + (lane & 7)) * 128 +
                                       ks * 32 + (((lane >> 3) & 1) << 4));
            LDSM_X2(b[ni][0], b[ni][1], bB + SMEM_SWZ(byte));
        }
#pragma unroll
        for (int mi = 0; mi < 2; mi++)
#pragma unroll
            for (int ni = 0; ni < 8; ni++)
                MMA16816(acc[mi][ni], a[mi][0], a[mi][1], a[mi][2], a[mi][3],
                         b[ni][0], b[ni][1]);
    }

#pragma unroll
    for (int mi = 0; mi < 2; mi++) {
#pragma unroll
        for (int hf = 0; hf < 2; hf++) {
            int r = wr * 32 + mi * 16 + (lane >> 2) + hf * 8;
            int s = ss_s[r], d = sd_s[r];
            const __half* xlp = g_xlrh + (size_t)s * 512;
            const __half* xrp = g_xlrh + (size_t)d * 512 + 256;
            float h0 = 0.f, h1 = 0.f;
#pragma unroll
            for (int ni = 0; ni < 8; ni++) {
                int c0 = wc * 64 + ni * 8 + (lane & 3) * 2;
                float2 xlv = __half22float2(*(const __half2*)(xlp + c0));
                float2 xrv = __half22float2(*(const __half2*)(xrp + c0));
                float z0 = acc[mi][ni][hf * 2 + 0] + xlv.x + xrv.x;
                float z1 = acc[mi][ni][hf * 2 + 1] + xlv.y + xrv.y;
                z0 = (z0 > 0.f) ? z0 : 0.2f * z0;
                z1 = (z1 > 0.f) ? z1 : 0.2f * z1;
                float pp = z0 * att_s[c0] + z1 * att_s[c0 + 1];
                if (ni < 4) h0 += pp; else h1 += pp;
            }
            h0 += __shfl_xor_sync(0xffffffffu, h0, 1);
            h0 += __shfl_xor_sync(0xffffffffu, h0, 2);
            h1 += __shfl_xor_sync(0xffffffffu, h1, 1);
            h1 += __shfl_xor_sync(0xffffffffu, h1, 2);
            if ((lane & 3) == 0) {
                sc_s[r * 8 + wc * 2]     = h0;
                sc_s[r * 8 + wc * 2 + 1] = h1;
            }
        }
    }
    __syncthreads();
#pragma unroll
    for (int p = 0; p < 2; p++) {
        int i = tid + (p << 9);
        int r = i >> 3;
        int e = row0 + r;
        if (e < ETOT) g_sc[(size_t)e * 8 + (i & 7)] = __expf(sc_s[i]);
    }
}

// ---------------- CSR build ------------------------------------------------------
__global__ void k_zero_icnt() {
    int i = blockIdx.x * blockDim.x + threadIdx.x;
    if (i < Nn) g_icnt[i] = 0;
}
__global__ void k_count(const int* __restrict__ dst) {
    int e = blockIdx.x * blockDim.x + threadIdx.x;
    if (e < Ee) atomicAdd(&g_icnt[dst[e]], 1);
}
__global__ void k_scan() {
    __shared__ int part[1024];
    int t = threadIdx.x;
    const int SEG = (Nn + 1023) / 1024;
    int base = t * SEG;
    int s = 0;
    for (int i = 0; i < SEG; i++) {
        int idx = base + i;
        if (idx < Nn) s += g_icnt[idx];
    }
    part[t] = s;
    __syncthreads();
    for (int off = 1; off < 1024; off <<= 1) {
        int v = (t >= off) ? part[t - off] : 0;
        __syncthreads();
        part[t] += v;
        __syncthreads();
    }
    int run = (t == 0) ? 0 : part[t - 1];
    for (int i = 0; i < SEG; i++) {
        int idx = base + i;
        if (idx < Nn) {
            g_rowptr[idx] = run;
            g_tmp[idx] = run;
            run += g_icnt[idx];
        }
    }
    if (t == 1023) g_rowptr[Nn] = run;
}
__global__ void k_scatter(const int* __restrict__ src, const int* __restrict__ dst) {
    int e = blockIdx.x * blockDim.x + threadIdx.x;
    if (e >= Ee) return;
    int d = dst[e];
    int pos = atomicAdd(&g_tmp[d], 1);
    g_adj[pos] = make_int2(src[e], e);
    g_pdst[pos] = d;
}
__global__ void k_loop_mean(const float* __restrict__ ew) {
    int d    = blockIdx.x * 8 + (threadIdx.x >> 5);
    int lane = threadIdx.x & 31;
    if (d >= Nn) return;
    int beg = g_rowptr[d], end = g_rowptr[d + 1];
    float s = 0.f;
    for (int i = beg; i < end; i++)
        s += ew[(size_t)g_adj[i].y * EDIMc + lane];
    g_loop[(size_t)d * EDIMc + lane] = s / fmaxf((float)(end - beg), 1.f);
}

// ---------------- per-node aggregation (pre-exp'ed weights, 4-way unroll) -------
__device__ __forceinline__ void acc_h8(float* acc, const __half* xp, float w) {
    uint4 raw = *(const uint4*)xp;
    const __half2* hp = (const __half2*)&raw;
    float2 f0 = __half22float2(hp[0]);
    float2 f1 = __half22float2(hp[1]);
    float2 f2 = __half22float2(hp[2]);
    float2 f3 = __half22float2(hp[3]);
    acc[0] += w * f0.x; acc[1] += w * f0.y;
    acc[2] += w * f1.x; acc[3] += w * f1.y;
    acc[4] += w * f2.x; acc[5] += w * f2.y;
    acc[6] += w * f3.x; acc[7] += w * f3.y;
}
__global__ void k_node() {
    __shared__ float s_st[512];
    int tid  = threadIdx.x;
    int d    = blockIdx.x * 8 + (tid >> 5);
    int lane = tid & 31;
    s_st[tid] = 0.f;
    s_st[tid + 256] = 0.f;
    __syncthreads();

    int beg = g_rowptr[d], end = g_rowptr[d + 1];
    const float* ssc = g_sc + (size_t)(Ee + d) * Hh;    // already exp'ed

    int hh = lane >> 2;
    int c0 = lane << 3;

    float den;
    float acc[8];
#pragma unroll
    for (int q = 0; q < 8; q++) acc[q] = 0.f;
    {
        float a = ssc[hh];
        den = a;
        acc_h8(acc, g_xlrh + (size_t)d * 512 + c0, a);
    }
    int i = beg;
    for (; i + 3 < end; i += 4) {
        int s0i = g_adj[i].x,     s1i = g_adj[i + 1].x;
        int s2i = g_adj[i + 2].x, s3i = g_adj[i + 3].x;
        float w0 = g_sc[(size_t)i * Hh + hh];
        float w1 = g_sc[(size_t)(i + 1) * Hh + hh];
        float w2 = g_sc[(size_t)(i + 2) * Hh + hh];
        float w3 = g_sc[(size_t)(i + 3) * Hh + hh];
        den += (w0 + w1) + (w2 + w3);
        acc_h8(acc, g_xlrh + (size_t)s0i * 512 + c0, w0);
        acc_h8(acc, g_xlrh + (size_t)s1i * 512 + c0, w1);
        acc_h8(acc, g_xlrh + (size_t)s2i * 512 + c0, w2);
        acc_h8(acc, g_xlrh + (size_t)s3i * 512 + c0, w3);
    }
    for (; i < end; i++) {
        int s0i = g_adj[i].x;
        float w0 = g_sc[(size_t)i * Hh + hh];
        den += w0;
        acc_h8(acc, g_xlrh + (size_t)s0i * 512 + c0, w0);
    }
    float inv = 1.f / den;
#pragma unroll
    for (int q = 0; q < 8; q++) acc[q] *= inv;

    float4* op = (float4*)(g_agg + (size_t)d * DIMc + c0);
    op[0] = make_float4(acc[0], acc[1], acc[2], acc[3]);
    op[1] = make_float4(acc[4], acc[5], acc[6], acc[7]);

#pragma unroll
    for (int q = 0; q < 8; q++) {
        atomicAdd(&s_st[c0 + q], acc[q]);
        atomicAdd(&s_st[256 + c0 + q], acc[q] * acc[q]);
    }
    __syncthreads();
    if (tid < 256) {
        atomicAdd(&g_sum[tid], s_st[tid]);
        atomicAdd(&g_sumsq[tid], s_st[tid + 256]);
    }
}

// ---------------- BatchNorm apply (vectorized, 4 cols/thread) --------------------
template<bool PACK>
__global__ void k_bnapply(const float* __restrict__ X, const float* __restrict__ gam,
                          const float* __restrict__ bet, const float* __restrict__ res,
                          float* __restrict__ out) {
    int i4 = blockIdx.x * blockDim.x + threadIdx.x;
    if (i4 >= Nn * DIMc / 4) return;
    int i = i4 << 2;
    int c = i & (DIMc - 1);
    float4 xv = *(const float4*)&X[i];
    float4 rv = *(const float4*)&res[i];
    float vo[4];
    float xs[4] = {xv.x, xv.y, xv.z, xv.w};
    float rs[4] = {rv.x, rv.y, rv.z, rv.w};
#pragma unroll
    for (int q = 0; q < 4; q++) {
        int cc = c + q;
        float mu  = g_sum[cc]   * (1.f / Nn);
        float var = g_sumsq[cc] * (1.f / Nn) - mu * mu;
        float y = (xs[q] - mu) * rsqrtf(var + 1e-5f) * gam[cc] + bet[cc];
        y = (y > 0.f) ? y : 0.01f * y;
        vo[q] = rs[q] + y;
    }
    *(float4*)&out[i] = make_float4(vo[0], vo[1], vo[2], vo[3]);
    if (PACK) {
        int r = i >> 8;
        size_t b = (size_t)r * 768 + c;
        __nv_bfloat162 h0 = __floats2bfloat162_rn(vo[0], vo[1]);
        __nv_bfloat162 h1 = __floats2bfloat162_rn(vo[2], vo[3]);
        __nv_bfloat162 l0 = __floats2bfloat162_rn(vo[0] - __bfloat162float(h0.x),
                                                  vo[1] - __bfloat162float(h0.y));
        __nv_bfloat162 l1 = __floats2bfloat162_rn(vo[2] - __bfloat162float(h1.x),
                                                  vo[3] - __bfloat162float(h1.y));
        *(__nv_bfloat162*)&g_Apk[b]           = h0;
        *(__nv_bfloat162*)&g_Apk[b + 2]       = h1;
        *(__nv_bfloat162*)&g_Apk[b + 256]     = l0;
        *(__nv_bfloat162*)&g_Apk[b + 258]     = l1;
        *(__nv_bfloat162*)&g_Apk[b + 512]     = h0;
        *(__nv_bfloat162*)&g_Apk[b + 514]     = h1;
    }
}

// ---------------- host orchestration ----------------------------------------------
static inline int cdiv(int a, int b) { return (a + b - 1) / b; }

extern "C" void kernel_launch(void* const* d_in, const int* in_sizes, int n_in,
                              void* d_out, int out_size) {
    const float* nf    = (const float*)d_in[0];
    const int*   ei    = (const int*)  d_in[1];
    const float* ew    = (const float*)d_in[2];
    const float* g1_Wl = (const float*)d_in[3];
    const float* g1_Wr = (const float*)d_in[4];
    const float* g1_We = (const float*)d_in[5];
    const float* g1_at = (const float*)d_in[6];
    const float* g2_Wl = (const float*)d_in[8];
    const float* g2_Wr = (const float*)d_in[9];
    const float* g2_We = (const float*)d_in[10];
    const float* g2_at = (const float*)d_in[11];
    const float* n1_g  = (const float*)d_in[13];
    const float* n1_b  = (const float*)d_in[14];
    const float* n2_g  = (const float*)d_in[15];
    const float* n2_b  = (const float*)d_in[16];
    const float* n3_g  = (const float*)d_in[17];
    const float* n3_b  = (const float*)d_in[18];
    const float* ff_W1 = (const float*)d_in[19];
    const float* ff_b1 = (const float*)d_in[20];
    const float* ff_W2 = (const float*)d_in[21];
    const int* src = ei;
    const int* dst = ei + Ee;
    float* out = (float*)d_out;

    void* p;
    cudaGetSymbolAddress(&p, g_agg);  float* agg  = (float*)p;
    cudaGetSymbolAddress(&p, g_h1);   float* h1   = (float*)p;
    cudaGetSymbolAddress(&p, g_h2);   float* h2   = (float*)p;
    cudaGetSymbolAddress(&p, g_ff2);  float* ff2  = (float*)p;
    cudaGetSymbolAddress(&p, g_Apk);  __nv_bfloat16* Apk = (__nv_bfloat16*)p;
    cudaGetSymbolAddress(&p, g_Fpk);  __nv_bfloat16* Fpk = (__nv_bfloat16*)p;
    cudaGetSymbolAddress(&p, g_EApk); __nv_bfloat16* EApk = (__nv_bfloat16*)p;
    cudaGetSymbolAddress(&p, g_Wpk);  __nv_bfloat16* Wpk = (__nv_bfloat16*)p;

    cudaFuncSetAttribute(gemm_pk<0>, cudaFuncAttributeMaxDynamicSharedMemorySize, GEMM_SMEM_PK);
    cudaFuncSetAttribute(gemm_pk<1>, cudaFuncAttributeMaxDynamicSharedMemorySize, GEMM_SMEM_PK);
    cudaFuncSetAttribute(gemm_pk<2>, cudaFuncAttributeMaxDynamicSharedMemorySize, GEMM_SMEM_PK);
    cudaFuncSetAttribute(gemm_pk<3>, cudaFuncAttributeMaxDynamicSharedMemorySize, GEMM_SMEM_PK);
    cudaFuncSetAttribute(gemm_score, cudaFuncAttributeMaxDynamicSharedMemorySize, SC_SMEM);

    cudaStream_t sd = 0;
    cudaEvent_t ev0 = nullptr, ev1 = nullptr;
    cudaStreamCreateWithFlags(&sd, cudaStreamNonBlocking);
    cudaEventCreateWithFlags(&ev0, cudaEventDisableTiming);
    cudaEventCreateWithFlags(&ev1, cudaEventDisableTiming);

    // ---- fork: CSR + edge-attr chain on side stream ----
    cudaEventRecord(ev0, 0);
    cudaStreamWaitEvent(sd, ev0, 0);
    k_zero_icnt<<<cdiv(Nn, 256), 256, 0, sd>>>();
    k_count<<<cdiv(Ee, 256), 256, 0, sd>>>(dst);
    k_scan<<<1, 1024, 0, sd>>>();
    k_scatter<<<cdiv(Ee, 256), 256, 0, sd>>>(src, dst);
    k_loop_mean<<<cdiv(Nn, 8), 256, 0, sd>>>(ew);
    k_pack_ea<<<cdiv(ETOT * EDIMc, 256), 256, 0, sd>>>(ew);
    cudaEventRecord(ev1, sd);

    // ---- main stream: weight packs, node pack, xlr GEMM ----
    k_packT_all<<<cdiv(802816, 256), 256>>>(g1_Wl, g1_Wr, g1_We, g2_Wl, g2_Wr, g2_We,
                                            ff_W1, ff_W2, Wpk);
    k_pack_node<<<cdiv(Nn * DIMc, 256), 256>>>(nf, Apk, Nn, DIMc);

    dim3 gXLR(4, cdiv(Nn, 128));
    int nbScore = cdiv(ETOT, 128);
    int nbNode  = cdiv(Nn, 8);

    gemm_pk<2><<<gXLR, 256, GEMM_SMEM_PK>>>(Apk, Wpk + OWLR1, nullptr, nullptr, Nn, 768, 512);

    // ---- join ----
    cudaStreamWaitEvent(0, ev1, 0);

    // ---- block 1 ----
    gemm_score<<<nbScore, 512, SC_SMEM>>>(EApk, Wpk + OWE1, g1_at);
    k_node<<<nbNode, 256>>>();
    k_bnapply<true><<<cdiv(Nn * DIMc / 4, 256), 256>>>(agg, n1_g, n1_b, nf, h1);

    // ---- block 2 ----
    gemm_pk<2><<<gXLR, 256, GEMM_SMEM_PK>>>(Apk, Wpk + OWLR2, nullptr, nullptr, Nn, 768, 512);
    gemm_score<<<nbScore, 512, SC_SMEM>>>(EApk, Wpk + OWE2, g2_at);
    k_node<<<nbNode, 256>>>();
    k_bnapply<true><<<cdiv(Nn * DIMc / 4, 256), 256>>>(agg, n2_g, n2_b, h1, h2);

    // ---- feed-forward ----
    dim3 gF1(8, cdiv(Nn, 128));
    gemm_pk<1><<<gF1, 256, GEMM_SMEM_PK>>>(Apk, Wpk + OW1, ff_b1, nullptr, Nn, 768, DFFc);
    dim3 gF2(2, cdiv(Nn, 128));
    gemm_pk<3><<<gF2, 256, GEMM_SMEM_PK>>>(Fpk, Wpk + OW2, nullptr, ff2, Nn, 3072, DIMc);
    k_bnapply<false><<<cdiv(Nn * DIMc / 4, 256), 256>>>(ff2, n3_g, n3_b, h2, out);
}